// round 12
// baseline (speedup 1.0000x reference)
#include <cuda_runtime.h>
#include <math.h>
#include <stdint.h>

#define IM     256
#define MTOT   184320
#define ORTHO  (1.0f/256.0f)
#define NSPLIT 72
#define ADJ_MPER (MTOT/NSPLIT)   // 2560
#define ADJ_ST   (ADJ_MPER/16)   // 160
#define NKST     (MTOT/16)       // 11520
#define NMT      (MTOT/128)      // 1440

// ---------------- static scratch -------------------------------------------
__device__ float  g_FB[4*16*4096];                  // fwd B frag tiles (1 MB)
__device__ float  g_FA[(size_t)NMT*16*4096];        // fwd A frag tiles (377 MB)
__device__ float  g_AA[(size_t)NKST*2*4096];        // adj A frag tiles (377 MB)
__device__ float2 g_S1x[MTOT], g_S8x[MTOT];
__device__ float2 g_S1y[MTOT], g_S8y[MTOT], g_S64y[MTOT], g_S128y[MTOT];
__device__ float2 g_PCH[(size_t)MTOT*16];           // conj(T0x*S16x^j)
__device__ float2 g_PXU[(size_t)MTOT*16];           // ut0: T0x*S1x^s ; ut1: S1x^s
__device__ float2 g_PYB[(size_t)MTOT*16];           // b0: S1y^s ; b1: S128y*S1y^s
__device__ float2 g_E0[MTOT];
__device__ float  g_P[(size_t)8*NSPLIT*128*128];    // adjoint partials

// ---------------- helpers --------------------------------------------------
__device__ __forceinline__ float2 cmulf(float2 a, float2 b) {
    return make_float2(a.x*b.x - a.y*b.y, a.x*b.y + a.y*b.x);
}
__device__ __forceinline__ float2 conjf(float2 a) { return make_float2(a.x, -a.y); }
__device__ __forceinline__ float tf32f(float x) {
    uint32_t r; asm("cvt.rna.tf32.f32 %0, %1;" : "=r"(r) : "f"(x));
    return __uint_as_float(r);
}
__device__ __forceinline__ float2 cpow4(float2 b, int e) {
    float2 r = make_float2(1.f, 0.f);
#pragma unroll
    for (int i = 0; i < 4; i++) { if (e & (1 << i)) r = cmulf(r, b); b = cmulf(b, b); }
    return r;
}
__device__ __forceinline__ void mma8(float* d, const uint32_t* a, const uint32_t* b) {
    asm volatile(
        "mma.sync.aligned.m16n8k8.row.col.f32.tf32.tf32.f32 "
        "{%0,%1,%2,%3}, {%4,%5,%6,%7}, {%8,%9}, {%0,%1,%2,%3};"
        : "+f"(d[0]), "+f"(d[1]), "+f"(d[2]), "+f"(d[3])
        : "r"(a[0]), "r"(a[1]), "r"(a[2]), "r"(a[3]), "r"(b[0]), "r"(b[1]));
}
__device__ __forceinline__ uint32_t su32(const void* p) {
    uint32_t a; asm("{ .reg .u64 t; cvta.to.shared.u64 t, %1; cvt.u32.u64 %0, t; }" : "=r"(a) : "l"(p));
    return a;
}
__device__ __forceinline__ void cp16(uint32_t saddr, const void* g) {
    asm volatile("cp.async.cg.shared.global [%0], [%1], 16;" :: "r"(saddr), "l"(g));
}
// A-frag float index for element (r, k) of a 128x32 tile (partition-agnostic)
__device__ __forceinline__ int afidx(int r, int k) {
    int ks = k >> 3, kl = k & 3, kh = (k >> 2) & 1;
    int rid = ((r >> 6) << 5) | (((r >> 4) & 3) << 3) | (r & 7);
    int p = (r >> 3) & 1;
    return (ks * 256 + rid * 4 + kl) * 4 + p + 2 * kh;
}
// B-frag float index for element (k, n) of a 32x128 tile
__device__ __forceinline__ int bfidx(int k, int n) {
    int ks = k >> 3, kl2 = k & 3, h = (k >> 2) & 1;
    return (ks * 512 + n * 4 + kl2) * 2 + h;
}

// ---------------- prep kernels ---------------------------------------------
__global__ __launch_bounds__(256) void prep_tab(const float* __restrict__ kxs,
                                                const float* __restrict__ kys)
{
    int m = blockIdx.x * 256 + threadIdx.x;
    float s, c;
    float kx = kxs[m], ky = kys[m];
    sincosf(kx, &s, &c);
    float2 S1 = make_float2(c, s);
    float2 S2 = cmulf(S1,S1), S4 = cmulf(S2,S2), S8 = cmulf(S4,S4);
    float2 S16 = cmulf(S8,S8), S32 = cmulf(S16,S16), S64 = cmulf(S32,S32);
    float2 S128 = cmulf(S64,S64);
    float2 T0 = conjf(S128);
    g_S1x[m] = S1; g_S8x[m] = S8;
    float2 q = T0;
#pragma unroll
    for (int j = 0; j < 16; j++) { g_PCH[(size_t)m*16 + j] = conjf(q); q = cmulf(q, S16); }
    float2 p = make_float2(1.f, 0.f);
#pragma unroll
    for (int s8 = 0; s8 < 8; s8++) {
        g_PXU[(size_t)m*16 + s8]     = cmulf(T0, p);
        g_PXU[(size_t)m*16 + 8 + s8] = p;
        p = cmulf(p, S1);
    }
    sincosf(ky, &s, &c);
    S1 = make_float2(c, s);
    S2 = cmulf(S1,S1); S4 = cmulf(S2,S2); S8 = cmulf(S4,S4);
    S16 = cmulf(S8,S8); S32 = cmulf(S16,S16); S64 = cmulf(S32,S32);
    S128 = cmulf(S64,S64);
    g_S1y[m] = S1; g_S8y[m] = S8; g_S64y[m] = S64; g_S128y[m] = S128;
    p = make_float2(1.f, 0.f);
#pragma unroll
    for (int s8 = 0; s8 < 8; s8++) {
        g_PYB[(size_t)m*16 + s8]     = p;
        g_PYB[(size_t)m*16 + 8 + s8] = cmulf(S128, p);
        p = cmulf(p, S1);
    }
}

__global__ __launch_bounds__(256) void prep_bf(const float2* __restrict__ img)
{
    int idx = blockIdx.x * 256 + threadIdx.x;
    int k = idx >> 9, n = idx & 511;
    int v = n & 255, u = k & 255;
    float2 g = img[u * 256 + v];
    float val = (n < 256) ? ((k < 256) ? g.x : -g.y)
                          : ((k < 256) ? g.y :  g.x);
    int nt = n >> 7, nn = n & 127, ch = k >> 5, kk = k & 31;
    g_FB[(nt * 16 + ch) * 4096 + bfidx(kk, nn)] = tf32f(val);
}

__global__ __launch_bounds__(128) void prep_fa()
{
    __shared__ float tile[4096];
    const int tid = threadIdx.x, gh = tid & 1, grow = tid >> 1;
    const int mtile = blockIdx.x, ch = blockIdx.y;
    const int m0 = mtile * 128;
    const bool iscos = (ch < 8);
    const int j = ((2 * ch) & 15) + gh;
#pragma unroll
    for (int rs = 0; rs < 2; rs++) {
        const int r = grow + 64 * rs, m = m0 + r;
        float2 cur = g_PCH[(size_t)m * 16 + j];
        const float2 st = conjf(g_S1x[m]);
#pragma unroll
        for (int q = 0; q < 16; q++) {
            tile[afidx(r, 16 * gh + q)] = tf32f(iscos ? cur.x : cur.y);
            cur = cmulf(cur, st);
        }
    }
    __syncthreads();
    float4* dst = (float4*)(g_FA + ((size_t)mtile * 16 + ch) * 4096);
    const float4* src = (const float4*)tile;
#pragma unroll
    for (int i = 0; i < 8; i++) dst[i * 128 + tid] = src[i * 128 + tid];
}

__global__ __launch_bounds__(128) void prep_aa()
{
    __shared__ float tile[4096];
    const int tid = threadIdx.x, gm = tid >> 3, sub = tid & 7;
    const int kst = blockIdx.x, ut = blockIdx.y;
    const int m = kst * 16 + gm;
    float2 cur = g_PXU[(size_t)m * 16 + ut * 8 + sub];
    const float2 stp = g_S8x[m];
#pragma unroll
    for (int q = 0; q < 16; q++) {
        const int u = sub + 8 * q;
        tile[afidx(u, 2 * gm)]     = tf32f(cur.x);
        tile[afidx(u, 2 * gm + 1)] = tf32f(cur.y);
        cur = cmulf(cur, stp);
    }
    __syncthreads();
    float4* dst = (float4*)(g_AA + ((size_t)kst * 2 + ut) * 4096);
    const float4* src = (const float4*)tile;
#pragma unroll
    for (int i = 0; i < 8; i++) dst[i * 128 + tid] = src[i * 128 + tid];
}

// ---------------------------------------------------------------------------
// Forward GEMM: 256 threads, 8 warps (4 wm x 2 wn), warp tile 32x64,
// both operands cp.async (triple buffer). Fused Ey-reduce + blend -> g_E0.
// ---------------------------------------------------------------------------
__global__ __launch_bounds__(256, 2)
void fwd_gemm(const float2* __restrict__ yrad, const float* __restrict__ lamp,
              const float* __restrict__ kxs, const float* __restrict__ kys)
{
    extern __shared__ float sh[];
    float* As = sh;                       // 3 x 4096
    float* Bs = sh + 12288;               // 3 x 4096
    float2* t_acc = (float2*)(sh + 24576);

    const int tid = threadIdx.x, lane = tid & 31, wid = tid >> 5;
    const int wm = wid >> 1, wn = wid & 1;
    const int mtile = blockIdx.x, m0 = mtile * 128;

    if (tid < 128) { t_acc[tid] = make_float2(0.f, 0.f); t_acc[128 + tid] = make_float2(0.f, 0.f); }

    float acc[2][8][4];
#pragma unroll
    for (int i = 0; i < 2; i++)
#pragma unroll
        for (int j = 0; j < 8; j++)
#pragma unroll
            for (int q = 0; q < 4; q++) acc[i][j][q] = 0.f;

    // precomputed A-frag rowids for fm=0,1: r = wm*32 + fm*16 + (lane>>2)
    int rid[2];
#pragma unroll
    for (int fm = 0; fm < 2; fm++) {
        int r = wm * 32 + fm * 16 + (lane >> 2);
        rid[fm] = ((r >> 6) << 5) | (((r >> 4) & 3) << 3) | (r & 7);
    }

#define FWD_FETCH(ls_) do {                                                     \
    if ((ls_) < 64) {                                                           \
        int b_ = (ls_) % 3;                                                     \
        const float* sA = g_FA + ((size_t)mtile * 16 + ((ls_) & 15)) * 4096;    \
        const float* sB = g_FB + ((((ls_) >> 4) * 16 + ((ls_) & 15))) * 4096;   \
        uint32_t dA = su32(As + b_ * 4096), dB = su32(Bs + b_ * 4096);          \
        for (int i_ = 0; i_ < 4; i_++) {                                        \
            cp16(dA + (i_ * 256 + tid) * 16, sA + (i_ * 256 + tid) * 4);        \
            cp16(dB + (i_ * 256 + tid) * 16, sB + (i_ * 256 + tid) * 4);        \
        }                                                                       \
    }                                                                           \
    asm volatile("cp.async.commit_group;");                                     \
} while (0)

    FWD_FETCH(0);
    FWD_FETCH(1);
    asm volatile("cp.async.wait_group 1;");
    __syncthreads();

    for (int ls = 0; ls < 64; ls++) {
        const int b = ls % 3, nt = ls >> 4, ch = ls & 15;
        const float4* Af = (const float4*)(As + b * 4096);
        const float2* Bf = (const float2*)(Bs + b * 4096);
#pragma unroll
        for (int ks = 0; ks < 4; ks++) {
            float4 av[2];
#pragma unroll
            for (int fm = 0; fm < 2; fm++)
                av[fm] = Af[ks * 256 + rid[fm] * 4 + (lane & 3)];
#pragma unroll
            for (int fn = 0; fn < 8; fn++) {
                float2 bv = Bf[ks * 512 + (wn * 64 + fn * 8 + (lane >> 2)) * 4 + (lane & 3)];
#pragma unroll
                for (int fm = 0; fm < 2; fm++)
                    mma8(acc[fm][fn], (const uint32_t*)&av[fm], (const uint32_t*)&bv);
            }
        }
        if (ch == 15) {   // fused Ey-weighted reduction for this nt
#pragma unroll
            for (int fm = 0; fm < 2; fm++)
#pragma unroll
            for (int cp = 0; cp < 2; cp++) {
                const int rl = wm * 32 + fm * 16 + cp * 8 + (lane >> 2);
                const int m = m0 + rl;
                const float2 S1c  = conjf(g_S1y[m]);
                const float2 S64c = conjf(g_S64y[m]);
                const float2 EYp  = g_S128y[m];
                const int a2 = ((nt & 1) << 1) | wn;
                float2 S2c = cmulf(S1c, S1c);
                float2 pb = cmulf(cmulf(EYp, cpow4(S64c, a2)), cpow4(S2c, lane & 3));
                float2 S8c = cmulf(S2c, S2c); S8c = cmulf(S8c, S8c);
                float tx = 0.f, ty = 0.f;
#pragma unroll
                for (int fn = 0; fn < 8; fn++) {
                    float v0 = acc[fm][fn][cp * 2 + 0];
                    float v1 = acc[fm][fn][cp * 2 + 1];
                    float2 p1 = cmulf(pb, S1c);
                    if (nt < 2) { tx += v0 * pb.x + v1 * p1.x;  ty += v0 * pb.y + v1 * p1.y; }
                    else        { tx -= v0 * pb.y + v1 * p1.y;  ty += v0 * pb.x + v1 * p1.x; }
                    pb = cmulf(pb, S8c);
                }
                tx += __shfl_xor_sync(0xffffffffu, tx, 1);
                ty += __shfl_xor_sync(0xffffffffu, ty, 1);
                tx += __shfl_xor_sync(0xffffffffu, tx, 2);
                ty += __shfl_xor_sync(0xffffffffu, ty, 2);
                if ((lane & 3) == 0) {
                    t_acc[wn * 128 + rl].x += tx;
                    t_acc[wn * 128 + rl].y += ty;
                }
            }
#pragma unroll
            for (int i = 0; i < 2; i++)
#pragma unroll
                for (int j = 0; j < 8; j++)
#pragma unroll
                    for (int q = 0; q < 4; q++) acc[i][j][q] = 0.f;
        }
        FWD_FETCH(ls + 2);
        asm volatile("cp.async.wait_group 1;");
        __syncthreads();
    }

    if (tid < 128) {
        const int m = m0 + tid;
        float2 t = make_float2(t_acc[tid].x + t_acc[128 + tid].x,
                               t_acc[tid].y + t_acc[128 + tid].y);
        const float lam = 1.0f / (1.0f + expf(-lamp[0]));
        const float kx = kxs[m], ky = kys[m];
        const float dcf = sqrtf(kx * kx + ky * ky);
        const int sp = m / 640, sam = m - sp * 640;
        const float2 y = yrad[sam * 288 + sp];
        const float w = lam * dcf * ORTHO;
        float2 kdc = make_float2(fmaf(w, t.x, (1.f - lam) * y.x),
                                 fmaf(w, t.y, (1.f - lam) * y.y));
        g_E0[m] = cmulf(kdc, conjf(g_S128y[m]));
    }
}

// ---------------------------------------------------------------------------
// Adjoint GEMM: 256 threads, 8 warps (4 wm x 2 wn), warp tile 32x64.
// A via cp.async (triple buffer), B generated in-loop (double buffer).
// ---------------------------------------------------------------------------
__global__ __launch_bounds__(256, 2)
void adj_gemm()
{
    extern __shared__ float sh[];
    float* As = sh;            // 3 x 4096
    float* Bs = sh + 12288;    // 2 x 4096

    const int tid = threadIdx.x, lane = tid & 31, wid = tid >> 5;
    const int wm = wid >> 1, wn = wid & 1;
    const int split = blockIdx.x, ut = blockIdx.y, nt = blockIdx.z;
    const int gm = tid >> 4, sub = tid & 15;
    const bool isRe = (nt < 2);
    const int yb = nt & 1;
    const int bks = gm >> 2, bh = (gm >> 1) & 1, bkl = 2 * (gm & 1);
    const int bbase0 = (bks * 512 + bkl) * 2 + bh;
    const int bbase1 = (bks * 512 + bkl + 1) * 2 + bh;

    float acc[2][8][4];
#pragma unroll
    for (int i = 0; i < 2; i++)
#pragma unroll
        for (int j = 0; j < 8; j++)
#pragma unroll
            for (int q = 0; q < 4; q++) acc[i][j][q] = 0.f;

    int rid[2];
#pragma unroll
    for (int fm = 0; fm < 2; fm++) {
        int r = wm * 32 + fm * 16 + (lane >> 2);
        rid[fm] = ((r >> 6) << 5) | (((r >> 4) & 3) << 3) | (r & 7);
    }

#define ADJ_FETCH(st_) do {                                                         \
    if ((st_) < ADJ_ST) {                                                           \
        int b_ = (st_) % 3;                                                         \
        const float* sA = g_AA + (((size_t)(split * ADJ_ST + (st_)) * 2) + ut) * 4096; \
        uint32_t dA = su32(As + b_ * 4096);                                         \
        for (int i_ = 0; i_ < 4; i_++)                                              \
            cp16(dA + (i_ * 256 + tid) * 16, sA + (i_ * 256 + tid) * 4);            \
    }                                                                               \
    asm volatile("cp.async.commit_group;");                                         \
} while (0)

    float2 tE, tPy, tS8;
#define ADJ_TAB(st_) do {                                                   \
    int m_ = (split * ADJ_ST + (st_)) * 16 + gm;                            \
    tE  = g_E0[m_];                                                         \
    tPy = g_PYB[(size_t)m_ * 16 + yb * 8 + (sub & 7)];                      \
    tS8 = g_S8y[m_];                                                        \
} while (0)

    // thread covers n = sub + 16q (q 0..7), step S16 = S8^2
#define ADJ_GENB(st_) do {                                                  \
    float* Bp = Bs + ((st_) & 1) * 4096;                                    \
    float2 s16 = cmulf(tS8, tS8);                                           \
    float2 c0 = cmulf(tE, tPy);                                             \
    if (sub & 8) c0 = cmulf(c0, tS8);                                       \
    _Pragma("unroll")                                                       \
    for (int q2 = 0; q2 < 8; q2++) {                                        \
        int n0 = sub + 16 * q2;                                             \
        if (isRe) {                                                         \
            Bp[bbase0 + n0 * 8] = tf32f(c0.x);                              \
            Bp[bbase1 + n0 * 8] = tf32f(-c0.y);                             \
        } else {                                                            \
            Bp[bbase0 + n0 * 8] = tf32f(c0.y);                              \
            Bp[bbase1 + n0 * 8] = tf32f(c0.x);                              \
        }                                                                   \
        c0 = cmulf(c0, s16);                                                \
    }                                                                       \
} while (0)

    ADJ_FETCH(0);
    ADJ_FETCH(1);
    ADJ_TAB(0); ADJ_GENB(0);
    ADJ_TAB(1);
    asm volatile("cp.async.wait_group 1;");
    __syncthreads();

    for (int st = 0; st < ADJ_ST; st++) {
        if (st + 1 < ADJ_ST) ADJ_GENB(st + 1);
        if (st + 2 < ADJ_ST) ADJ_TAB(st + 2);
        {
            const float4* Af = (const float4*)(As + (st % 3) * 4096);
            const float2* Bf = (const float2*)(Bs + (st & 1) * 4096);
#pragma unroll
            for (int ks = 0; ks < 4; ks++) {
                float4 av[2];
#pragma unroll
                for (int fm = 0; fm < 2; fm++)
                    av[fm] = Af[ks * 256 + rid[fm] * 4 + (lane & 3)];
#pragma unroll
                for (int fn = 0; fn < 8; fn++) {
                    float2 bv = Bf[ks * 512 + (wn * 64 + fn * 8 + (lane >> 2)) * 4 + (lane & 3)];
#pragma unroll
                    for (int fm = 0; fm < 2; fm++)
                        mma8(acc[fm][fn], (const uint32_t*)&av[fm], (const uint32_t*)&bv);
                }
            }
        }
        ADJ_FETCH(st + 2);
        asm volatile("cp.async.wait_group 1;");
        __syncthreads();
    }

    float* outp = g_P + (size_t)((ut * 4 + nt) * NSPLIT + split) * 16384;
#pragma unroll
    for (int fm = 0; fm < 2; fm++)
#pragma unroll
    for (int cp = 0; cp < 2; cp++) {
        const int u = wm * 32 + fm * 16 + cp * 8 + (lane >> 2);
#pragma unroll
        for (int fn = 0; fn < 8; fn++) {
            const int n = wn * 64 + fn * 8 + 2 * (lane & 3);
            *(float2*)&outp[u * 128 + n] =
                make_float2(acc[fm][fn][cp * 2], acc[fm][fn][cp * 2 + 1]);
        }
    }
}

// ---------------------------------------------------------------------------
__global__ __launch_bounds__(256) void reduce_k(float* __restrict__ out)
{
    const int idx = blockIdx.x * 256 + threadIdx.x;
    const int ug = idx >> 9, ng = idx & 511;
    const int ut = ug >> 7, ul = ug & 127, nt = ng >> 7, nl = ng & 127;
    const float* p = g_P + (size_t)((ut * 4 + nt) * NSPLIT) * 16384 + ul * 128 + nl;
    float s = 0.f;
#pragma unroll 8
    for (int sp = 0; sp < NSPLIT; sp++) s += p[(size_t)sp * 16384];
    const int v = ng & 255, c = ng >> 8;
    out[(ug * 256 + v) * 2 + c] = s * ORTHO;
}

// ---------------------------------------------------------------------------
extern "C" void kernel_launch(void* const* d_in, const int* in_sizes, int n_in,
                              void* d_out, int out_size)
{
    const float2* img  = (const float2*)d_in[0];
    const float2* yrad = (const float2*)d_in[1];
    const float*  lamp = (const float*)d_in[2];
    const float*  ktr  = (const float*)d_in[3];
    const float*  kxs  = ktr;
    const float*  kys  = ktr + MTOT;
    float* out = (float*)d_out;

    const int FWD_SMEM = (24576 + 512) * 4;    // 100352 B
    const int ADJ_SMEM = 20480 * 4;            // 81920 B
    cudaFuncSetAttribute(fwd_gemm, cudaFuncAttributeMaxDynamicSharedMemorySize, FWD_SMEM);
    cudaFuncSetAttribute(adj_gemm, cudaFuncAttributeMaxDynamicSharedMemorySize, ADJ_SMEM);

    prep_tab<<<MTOT/256, 256>>>(kxs, kys);
    prep_bf<<<1024, 256>>>(img);
    prep_fa<<<dim3(NMT, 16), 128>>>();
    prep_aa<<<dim3(NKST, 2), 128>>>();
    fwd_gemm<<<NMT, 256, FWD_SMEM>>>(yrad, lamp, kxs, kys);
    adj_gemm<<<dim3(NSPLIT, 2, 4), 256, ADJ_SMEM>>>();
    reduce_k<<<512, 256>>>(out);
}

// round 13
// speedup vs baseline: 1.0626x; 1.0626x over previous
#include <cuda_runtime.h>
#include <math.h>
#include <stdint.h>

#define IM     256
#define MTOT   184320
#define ORTHO  (1.0f/256.0f)
#define NSPLIT 72
#define ADJ_MPER (MTOT/NSPLIT)   // 2560
#define ADJ_ST   (ADJ_MPER/16)   // 160
#define NKST     (MTOT/16)       // 11520
#define NMT      (MTOT/128)      // 1440

// ---------------- static scratch -------------------------------------------
__device__ float  g_FB[4*16*4096];                  // fwd B frag tiles (1 MB)
__device__ float  g_FA[(size_t)NMT*16*4096];        // fwd A frag tiles (377 MB)
__device__ float  g_AA[(size_t)NKST*2*4096];        // adj A frag tiles (377 MB)
__device__ float2 g_S1x[MTOT], g_S8x[MTOT];
__device__ float2 g_S1y[MTOT], g_S8y[MTOT], g_S64y[MTOT], g_S128y[MTOT];
__device__ float2 g_PCH[(size_t)MTOT*16];           // conj(T0x*S16x^j)
__device__ float2 g_PXU[(size_t)MTOT*16];           // ut0: T0x*S1x^s ; ut1: S1x^s
__device__ float2 g_PYB[(size_t)MTOT*16];           // b0: S1y^s ; b1: S128y*S1y^s
__device__ float2 g_E0[MTOT];
__device__ float  g_P[(size_t)8*NSPLIT*128*128];    // adjoint partials

// ---------------- helpers --------------------------------------------------
__device__ __forceinline__ float2 cmulf(float2 a, float2 b) {
    return make_float2(a.x*b.x - a.y*b.y, a.x*b.y + a.y*b.x);
}
__device__ __forceinline__ float2 conjf(float2 a) { return make_float2(a.x, -a.y); }
__device__ __forceinline__ float tf32f(float x) {
    uint32_t r; asm("cvt.rna.tf32.f32 %0, %1;" : "=r"(r) : "f"(x));
    return __uint_as_float(r);
}
__device__ __forceinline__ float2 cpow4(float2 b, int e) {
    float2 r = make_float2(1.f, 0.f);
#pragma unroll
    for (int i = 0; i < 4; i++) { if (e & (1 << i)) r = cmulf(r, b); b = cmulf(b, b); }
    return r;
}
__device__ __forceinline__ void mma8(float* d, const uint32_t* a, const uint32_t* b) {
    asm volatile(
        "mma.sync.aligned.m16n8k8.row.col.f32.tf32.tf32.f32 "
        "{%0,%1,%2,%3}, {%4,%5,%6,%7}, {%8,%9}, {%0,%1,%2,%3};"
        : "+f"(d[0]), "+f"(d[1]), "+f"(d[2]), "+f"(d[3])
        : "r"(a[0]), "r"(a[1]), "r"(a[2]), "r"(a[3]), "r"(b[0]), "r"(b[1]));
}
__device__ __forceinline__ uint32_t su32(const void* p) {
    uint32_t a; asm("{ .reg .u64 t; cvta.to.shared.u64 t, %1; cvt.u32.u64 %0, t; }" : "=r"(a) : "l"(p));
    return a;
}
__device__ __forceinline__ void cp16(uint32_t saddr, const void* g) {
    asm volatile("cp.async.cg.shared.global [%0], [%1], 16;" :: "r"(saddr), "l"(g));
}
// A-frag float index for element (r, k) of a 128x32 tile
__device__ __forceinline__ int afidx(int r, int k) {
    int ks = k >> 3, kl = k & 3, kh = (k >> 2) & 1;
    int rid = ((r >> 6) << 5) | (((r >> 4) & 3) << 3) | (r & 7);
    int p = (r >> 3) & 1;
    return (ks * 256 + rid * 4 + kl) * 4 + p + 2 * kh;
}
// Paired B-frag float index for element (k, n) of a 32x128 tile:
// float4 = { (klo,n0), (khi,n0), (klo,n0+8), (khi,n0+8) }
__device__ __forceinline__ int bfidx(int k, int n) {
    int ks = k >> 3, kl2 = k & 3, h = (k >> 2) & 1;
    int pg = (n >> 4) & 7, r8 = n & 7, nh = (n >> 3) & 1;
    return (((ks * 8 + pg) * 8 + r8) * 4 + kl2) * 4 + h + 2 * nh;
}

// ---------------- prep kernels ---------------------------------------------
__global__ __launch_bounds__(256) void prep_tab(const float* __restrict__ kxs,
                                                const float* __restrict__ kys)
{
    int m = blockIdx.x * 256 + threadIdx.x;
    float s, c;
    float kx = kxs[m], ky = kys[m];
    sincosf(kx, &s, &c);
    float2 S1 = make_float2(c, s);
    float2 S2 = cmulf(S1,S1), S4 = cmulf(S2,S2), S8 = cmulf(S4,S4);
    float2 S16 = cmulf(S8,S8), S32 = cmulf(S16,S16), S64 = cmulf(S32,S32);
    float2 S128 = cmulf(S64,S64);
    float2 T0 = conjf(S128);
    g_S1x[m] = S1; g_S8x[m] = S8;
    float2 q = T0;
#pragma unroll
    for (int j = 0; j < 16; j++) { g_PCH[(size_t)m*16 + j] = conjf(q); q = cmulf(q, S16); }
    float2 p = make_float2(1.f, 0.f);
#pragma unroll
    for (int s8 = 0; s8 < 8; s8++) {
        g_PXU[(size_t)m*16 + s8]     = cmulf(T0, p);
        g_PXU[(size_t)m*16 + 8 + s8] = p;
        p = cmulf(p, S1);
    }
    sincosf(ky, &s, &c);
    S1 = make_float2(c, s);
    S2 = cmulf(S1,S1); S4 = cmulf(S2,S2); S8 = cmulf(S4,S4);
    S16 = cmulf(S8,S8); S32 = cmulf(S16,S16); S64 = cmulf(S32,S32);
    S128 = cmulf(S64,S64);
    g_S1y[m] = S1; g_S8y[m] = S8; g_S64y[m] = S64; g_S128y[m] = S128;
    p = make_float2(1.f, 0.f);
#pragma unroll
    for (int s8 = 0; s8 < 8; s8++) {
        g_PYB[(size_t)m*16 + s8]     = p;
        g_PYB[(size_t)m*16 + 8 + s8] = cmulf(S128, p);
        p = cmulf(p, S1);
    }
}

__global__ __launch_bounds__(256) void prep_bf(const float2* __restrict__ img)
{
    int idx = blockIdx.x * 256 + threadIdx.x;
    int k = idx >> 9, n = idx & 511;
    int v = n & 255, u = k & 255;
    float2 g = img[u * 256 + v];
    float val = (n < 256) ? ((k < 256) ? g.x : -g.y)
                          : ((k < 256) ? g.y :  g.x);
    int nt = n >> 7, nn = n & 127, ch = k >> 5, kk = k & 31;
    g_FB[(nt * 16 + ch) * 4096 + bfidx(kk, nn)] = tf32f(val);
}

__global__ __launch_bounds__(128) void prep_fa()
{
    __shared__ float tile[4096];
    const int tid = threadIdx.x, gh = tid & 1, grow = tid >> 1;
    const int mtile = blockIdx.x, ch = blockIdx.y;
    const int m0 = mtile * 128;
    const bool iscos = (ch < 8);
    const int j = ((2 * ch) & 15) + gh;
#pragma unroll
    for (int rs = 0; rs < 2; rs++) {
        const int r = grow + 64 * rs, m = m0 + r;
        float2 cur = g_PCH[(size_t)m * 16 + j];
        const float2 st = conjf(g_S1x[m]);
#pragma unroll
        for (int q = 0; q < 16; q++) {
            tile[afidx(r, 16 * gh + q)] = tf32f(iscos ? cur.x : cur.y);
            cur = cmulf(cur, st);
        }
    }
    __syncthreads();
    float4* dst = (float4*)(g_FA + ((size_t)mtile * 16 + ch) * 4096);
    const float4* src = (const float4*)tile;
#pragma unroll
    for (int i = 0; i < 8; i++) dst[i * 128 + tid] = src[i * 128 + tid];
}

__global__ __launch_bounds__(128) void prep_aa()
{
    __shared__ float tile[4096];
    const int tid = threadIdx.x, gm = tid >> 3, sub = tid & 7;
    const int kst = blockIdx.x, ut = blockIdx.y;
    const int m = kst * 16 + gm;
    float2 cur = g_PXU[(size_t)m * 16 + ut * 8 + sub];
    const float2 stp = g_S8x[m];
#pragma unroll
    for (int q = 0; q < 16; q++) {
        const int u = sub + 8 * q;
        tile[afidx(u, 2 * gm)]     = tf32f(cur.x);
        tile[afidx(u, 2 * gm + 1)] = tf32f(cur.y);
        cur = cmulf(cur, stp);
    }
    __syncthreads();
    float4* dst = (float4*)(g_AA + ((size_t)kst * 2 + ut) * 4096);
    const float4* src = (const float4*)tile;
#pragma unroll
    for (int i = 0; i < 8; i++) dst[i * 128 + tid] = src[i * 128 + tid];
}

// ---------------------------------------------------------------------------
// Forward GEMM: 128 threads, 4 warps (2 wm x 2 wn), warp tile 64x64,
// both operands cp.async (triple buffer), B frags read as LDS.128 pairs.
// ---------------------------------------------------------------------------
__global__ __launch_bounds__(128)
void fwd_gemm(const float2* __restrict__ yrad, const float* __restrict__ lamp,
              const float* __restrict__ kxs, const float* __restrict__ kys)
{
    extern __shared__ float sh[];
    float* As = sh;                       // 3 x 4096
    float* Bs = sh + 12288;               // 3 x 4096
    float2* t_acc = (float2*)(sh + 24576);

    const int tid = threadIdx.x, lane = tid & 31, wid = tid >> 5;
    const int wm = wid >> 1, wn = wid & 1;
    const int mtile = blockIdx.x, m0 = mtile * 128;

    t_acc[tid]       = make_float2(0.f, 0.f);
    t_acc[128 + tid] = make_float2(0.f, 0.f);

    float acc[4][8][4];
#pragma unroll
    for (int i = 0; i < 4; i++)
#pragma unroll
        for (int j = 0; j < 8; j++)
#pragma unroll
            for (int q = 0; q < 4; q++) acc[i][j][q] = 0.f;

#define FWD_FETCH(ls_) do {                                                     \
    if ((ls_) < 64) {                                                           \
        int b_ = (ls_) % 3;                                                     \
        const float* sA = g_FA + ((size_t)mtile * 16 + ((ls_) & 15)) * 4096;    \
        const float* sB = g_FB + ((((ls_) >> 4) * 16 + ((ls_) & 15))) * 4096;   \
        uint32_t dA = su32(As + b_ * 4096), dB = su32(Bs + b_ * 4096);          \
        for (int i_ = 0; i_ < 8; i_++) {                                        \
            cp16(dA + (i_ * 128 + tid) * 16, sA + (i_ * 128 + tid) * 4);        \
            cp16(dB + (i_ * 128 + tid) * 16, sB + (i_ * 128 + tid) * 4);        \
        }                                                                       \
    }                                                                           \
    asm volatile("cp.async.commit_group;");                                     \
} while (0)

    FWD_FETCH(0);
    FWD_FETCH(1);
    asm volatile("cp.async.wait_group 1;");
    __syncthreads();

    for (int ls = 0; ls < 64; ls++) {
        const int b = ls % 3, nt = ls >> 4, ch = ls & 15;
        const float4* Af = (const float4*)(As + b * 4096);
        const float4* Bf = (const float4*)(Bs + b * 4096);
#pragma unroll
        for (int ks = 0; ks < 4; ks++) {
            float4 av[4];
#pragma unroll
            for (int fm = 0; fm < 4; fm++)
                av[fm] = Af[ks * 256 + (wm * 32 + fm * 8 + (lane >> 2)) * 4 + (lane & 3)];
#pragma unroll
            for (int pgl = 0; pgl < 4; pgl++) {
                float4 bq = Bf[((ks * 8 + wn * 4 + pgl) * 8 + (lane >> 2)) * 4 + (lane & 3)];
#pragma unroll
                for (int fm = 0; fm < 4; fm++) {
                    mma8(acc[fm][2 * pgl],     (const uint32_t*)&av[fm], (const uint32_t*)&bq.x);
                    mma8(acc[fm][2 * pgl + 1], (const uint32_t*)&av[fm], (const uint32_t*)&bq.z);
                }
            }
        }
        if (ch == 15) {   // fused Ey-weighted reduction for this nt
#pragma unroll
            for (int fm = 0; fm < 4; fm++)
#pragma unroll
            for (int cp = 0; cp < 2; cp++) {
                const int rl = wm * 64 + fm * 16 + cp * 8 + (lane >> 2);
                const int m = m0 + rl;
                const float2 S1c  = conjf(g_S1y[m]);
                const float2 S64c = conjf(g_S64y[m]);
                const float2 EYp  = g_S128y[m];
                const int a2 = ((nt & 1) << 1) | wn;
                float2 S2c = cmulf(S1c, S1c);
                float2 pb = cmulf(cmulf(EYp, cpow4(S64c, a2)), cpow4(S2c, lane & 3));
                float2 S8c = cmulf(S2c, S2c); S8c = cmulf(S8c, S8c);
                float tx = 0.f, ty = 0.f;
#pragma unroll
                for (int fn = 0; fn < 8; fn++) {
                    float v0 = acc[fm][fn][cp * 2 + 0];
                    float v1 = acc[fm][fn][cp * 2 + 1];
                    float2 p1 = cmulf(pb, S1c);
                    if (nt < 2) { tx += v0 * pb.x + v1 * p1.x;  ty += v0 * pb.y + v1 * p1.y; }
                    else        { tx -= v0 * pb.y + v1 * p1.y;  ty += v0 * pb.x + v1 * p1.x; }
                    pb = cmulf(pb, S8c);
                }
                tx += __shfl_xor_sync(0xffffffffu, tx, 1);
                ty += __shfl_xor_sync(0xffffffffu, ty, 1);
                tx += __shfl_xor_sync(0xffffffffu, tx, 2);
                ty += __shfl_xor_sync(0xffffffffu, ty, 2);
                if ((lane & 3) == 0) {
                    t_acc[wn * 128 + rl].x += tx;
                    t_acc[wn * 128 + rl].y += ty;
                }
            }
#pragma unroll
            for (int i = 0; i < 4; i++)
#pragma unroll
                for (int j = 0; j < 8; j++)
#pragma unroll
                    for (int q = 0; q < 4; q++) acc[i][j][q] = 0.f;
        }
        FWD_FETCH(ls + 2);
        asm volatile("cp.async.wait_group 1;");
        __syncthreads();
    }

    {
        const int m = m0 + tid;
        float2 t = make_float2(t_acc[tid].x + t_acc[128 + tid].x,
                               t_acc[tid].y + t_acc[128 + tid].y);
        const float lam = 1.0f / (1.0f + expf(-lamp[0]));
        const float kx = kxs[m], ky = kys[m];
        const float dcf = sqrtf(kx * kx + ky * ky);
        const int sp = m / 640, sam = m - sp * 640;
        const float2 y = yrad[sam * 288 + sp];
        const float w = lam * dcf * ORTHO;
        float2 kdc = make_float2(fmaf(w, t.x, (1.f - lam) * y.x),
                                 fmaf(w, t.y, (1.f - lam) * y.y));
        g_E0[m] = cmulf(kdc, conjf(g_S128y[m]));
    }
}

// ---------------------------------------------------------------------------
// Adjoint GEMM: 128 threads, warp 64x64. A via cp.async (triple buffer),
// B generated in-loop (double buffer) into paired layout; B reads LDS.128.
// ---------------------------------------------------------------------------
__global__ __launch_bounds__(128)
void adj_gemm()
{
    extern __shared__ float sh[];
    float* As = sh;            // 3 x 4096
    float* Bs = sh + 12288;    // 2 x 4096

    const int tid = threadIdx.x, lane = tid & 31, wid = tid >> 5;
    const int wm = wid >> 1, wn = wid & 1;
    const int split = blockIdx.x, ut = blockIdx.y, nt = blockIdx.z;
    const int gm = tid >> 3, sub = tid & 7;
    const bool isRe = (nt < 2);
    const int yb = nt & 1;
    // paired-layout store bases: k'=2gm,2gm+1 ; h = (gm>>1)&1, kl2 = 2*(gm&1)
    const int bks = gm >> 2, bh = (gm >> 1) & 1, bkl = 2 * (gm & 1);

    float acc[4][8][4];
#pragma unroll
    for (int i = 0; i < 4; i++)
#pragma unroll
        for (int j = 0; j < 8; j++)
#pragma unroll
            for (int q = 0; q < 4; q++) acc[i][j][q] = 0.f;

#define ADJ_FETCH(st_) do {                                                         \
    if ((st_) < ADJ_ST) {                                                           \
        int b_ = (st_) % 3;                                                         \
        const float* sA = g_AA + (((size_t)(split * ADJ_ST + (st_)) * 2) + ut) * 4096; \
        uint32_t dA = su32(As + b_ * 4096);                                         \
        for (int i_ = 0; i_ < 8; i_++)                                              \
            cp16(dA + (i_ * 128 + tid) * 16, sA + (i_ * 128 + tid) * 4);            \
    }                                                                               \
    asm volatile("cp.async.commit_group;");                                         \
} while (0)

    float2 tE, tPy, tS8;
#define ADJ_TAB(st_) do {                                                   \
    int m_ = (split * ADJ_ST + (st_)) * 16 + gm;                            \
    tE  = g_E0[m_];                                                         \
    tPy = g_PYB[(size_t)m_ * 16 + yb * 8 + sub];                            \
    tS8 = g_S8y[m_];                                                        \
} while (0)

    // thread covers n0 = sub+16q, n1 = n0+8, q = 0..7
#define ADJ_GENB(st_) do {                                                  \
    float* Bp = Bs + ((st_) & 1) * 4096;                                    \
    float2 s16 = cmulf(tS8, tS8);                                           \
    float2 c0 = cmulf(tE, tPy);                                             \
    float2 c1 = cmulf(c0, tS8);                                             \
    _Pragma("unroll")                                                       \
    for (int q2 = 0; q2 < 8; q2++) {                                        \
        int f4b = ((bks * 8 + q2) * 8 + sub) * 4 + bkl;                     \
        int F0 = 4 * f4b + bh, F1 = F0 + 4;                                 \
        if (isRe) {                                                         \
            Bp[F0]     = tf32f(c0.x);                                       \
            Bp[F1]     = tf32f(-c0.y);                                      \
            Bp[F0 + 2] = tf32f(c1.x);                                       \
            Bp[F1 + 2] = tf32f(-c1.y);                                      \
        } else {                                                            \
            Bp[F0]     = tf32f(c0.y);                                       \
            Bp[F1]     = tf32f(c0.x);                                       \
            Bp[F0 + 2] = tf32f(c1.y);                                       \
            Bp[F1 + 2] = tf32f(c1.x);                                       \
        }                                                                   \
        c0 = cmulf(c0, s16);                                                \
        c1 = cmulf(c1, s16);                                                \
    }                                                                       \
} while (0)

    ADJ_FETCH(0);
    ADJ_FETCH(1);
    ADJ_TAB(0); ADJ_GENB(0);
    ADJ_TAB(1);
    asm volatile("cp.async.wait_group 1;");
    __syncthreads();

    for (int st = 0; st < ADJ_ST; st++) {
        if (st + 1 < ADJ_ST) ADJ_GENB(st + 1);
        if (st + 2 < ADJ_ST) ADJ_TAB(st + 2);
        {
            const float4* Af = (const float4*)(As + (st % 3) * 4096);
            const float4* Bf = (const float4*)(Bs + (st & 1) * 4096);
#pragma unroll
            for (int ks = 0; ks < 4; ks++) {
                float4 av[4];
#pragma unroll
                for (int fm = 0; fm < 4; fm++)
                    av[fm] = Af[ks * 256 + (wm * 32 + fm * 8 + (lane >> 2)) * 4 + (lane & 3)];
#pragma unroll
                for (int pgl = 0; pgl < 4; pgl++) {
                    float4 bq = Bf[((ks * 8 + wn * 4 + pgl) * 8 + (lane >> 2)) * 4 + (lane & 3)];
#pragma unroll
                    for (int fm = 0; fm < 4; fm++) {
                        mma8(acc[fm][2 * pgl],     (const uint32_t*)&av[fm], (const uint32_t*)&bq.x);
                        mma8(acc[fm][2 * pgl + 1], (const uint32_t*)&av[fm], (const uint32_t*)&bq.z);
                    }
                }
            }
        }
        ADJ_FETCH(st + 2);
        asm volatile("cp.async.wait_group 1;");
        __syncthreads();
    }

    float* outp = g_P + (size_t)((ut * 4 + nt) * NSPLIT + split) * 16384;
#pragma unroll
    for (int fm = 0; fm < 4; fm++)
#pragma unroll
    for (int cp = 0; cp < 2; cp++) {
        const int u = wm * 64 + fm * 16 + cp * 8 + (lane >> 2);
#pragma unroll
        for (int fn = 0; fn < 8; fn++) {
            const int n = wn * 64 + fn * 8 + 2 * (lane & 3);
            *(float2*)&outp[u * 128 + n] =
                make_float2(acc[fm][fn][cp * 2], acc[fm][fn][cp * 2 + 1]);
        }
    }
}

// ---------------------------------------------------------------------------
__global__ __launch_bounds__(256) void reduce_k(float* __restrict__ out)
{
    const int idx = blockIdx.x * 256 + threadIdx.x;
    const int ug = idx >> 9, ng = idx & 511;
    const int ut = ug >> 7, ul = ug & 127, nt = ng >> 7, nl = ng & 127;
    const float* p = g_P + (size_t)((ut * 4 + nt) * NSPLIT) * 16384 + ul * 128 + nl;
    float s = 0.f;
#pragma unroll 8
    for (int sp = 0; sp < NSPLIT; sp++) s += p[(size_t)sp * 16384];
    const int v = ng & 255, c = ng >> 8;
    out[(ug * 256 + v) * 2 + c] = s * ORTHO;
}

// ---------------------------------------------------------------------------
extern "C" void kernel_launch(void* const* d_in, const int* in_sizes, int n_in,
                              void* d_out, int out_size)
{
    const float2* img  = (const float2*)d_in[0];
    const float2* yrad = (const float2*)d_in[1];
    const float*  lamp = (const float*)d_in[2];
    const float*  ktr  = (const float*)d_in[3];
    const float*  kxs  = ktr;
    const float*  kys  = ktr + MTOT;
    float* out = (float*)d_out;

    const int FWD_SMEM = (24576 + 512) * 4;    // 100352 B
    const int ADJ_SMEM = 20480 * 4;            // 81920 B
    cudaFuncSetAttribute(fwd_gemm, cudaFuncAttributeMaxDynamicSharedMemorySize, FWD_SMEM);
    cudaFuncSetAttribute(adj_gemm, cudaFuncAttributeMaxDynamicSharedMemorySize, ADJ_SMEM);

    prep_tab<<<MTOT/256, 256>>>(kxs, kys);
    prep_bf<<<1024, 256>>>(img);
    prep_fa<<<dim3(NMT, 16), 128>>>();
    prep_aa<<<dim3(NKST, 2), 128>>>();
    fwd_gemm<<<NMT, 128, FWD_SMEM>>>(yrad, lamp, kxs, kys);
    adj_gemm<<<dim3(NSPLIT, 2, 4), 128, ADJ_SMEM>>>();
    reduce_k<<<512, 256>>>(out);
}

// round 14
// speedup vs baseline: 1.6834x; 1.5841x over previous
#include <cuda_runtime.h>
#include <cuda_fp16.h>
#include <math.h>
#include <stdint.h>

#define IM     256
#define MTOT   184320
#define ORTHO  (1.0f/256.0f)
#define NSPLIT 72
#define ADJ_MPER (MTOT/NSPLIT)   // 2560
#define ADJ_ST   (ADJ_MPER/16)   // 160
#define NKST     (MTOT/16)       // 11520
#define NMT      (MTOT/128)      // 1440

// ---------------- static scratch -------------------------------------------
__device__ __half  g_FB[4*16*4096];                 // fwd B frag tiles (512 KB)
__device__ __half  g_FA[(size_t)NMT*16*4096];       // fwd A frag tiles (188 MB)
__device__ __half  g_AA[(size_t)NKST*2*4096];       // adj A frag tiles (188 MB)
__device__ float2 g_S1x[MTOT], g_S8x[MTOT];
__device__ float2 g_S1y[MTOT], g_S8y[MTOT], g_S64y[MTOT], g_S128y[MTOT];
__device__ float2 g_PCH[(size_t)MTOT*16];           // conj(T0x*S16x^j)
__device__ float2 g_PXU[(size_t)MTOT*16];           // ut0: T0x*S1x^s ; ut1: S1x^s
__device__ float2 g_PYB[(size_t)MTOT*16];           // b0: S1y^s ; b1: S128y*S1y^s
__device__ float2 g_E0[MTOT];
__device__ float  g_P[(size_t)8*NSPLIT*128*128];    // adjoint partials

// ---------------- helpers --------------------------------------------------
__device__ __forceinline__ float2 cmulf(float2 a, float2 b) {
    return make_float2(a.x*b.x - a.y*b.y, a.x*b.y + a.y*b.x);
}
__device__ __forceinline__ float2 conjf(float2 a) { return make_float2(a.x, -a.y); }
__device__ __forceinline__ float2 cpow4(float2 b, int e) {
    float2 r = make_float2(1.f, 0.f);
#pragma unroll
    for (int i = 0; i < 4; i++) { if (e & (1 << i)) r = cmulf(r, b); b = cmulf(b, b); }
    return r;
}
__device__ __forceinline__ void mma16(float* d, const uint32_t* a, const uint32_t* b) {
    asm volatile(
        "mma.sync.aligned.m16n8k16.row.col.f32.f16.f16.f32 "
        "{%0,%1,%2,%3}, {%4,%5,%6,%7}, {%8,%9}, {%0,%1,%2,%3};"
        : "+f"(d[0]), "+f"(d[1]), "+f"(d[2]), "+f"(d[3])
        : "r"(a[0]), "r"(a[1]), "r"(a[2]), "r"(a[3]), "r"(b[0]), "r"(b[1]));
}
__device__ __forceinline__ uint32_t su32(const void* p) {
    uint32_t a; asm("{ .reg .u64 t; cvta.to.shared.u64 t, %1; cvt.u32.u64 %0, t; }" : "=r"(a) : "l"(p));
    return a;
}
__device__ __forceinline__ void cp16(uint32_t saddr, const void* g) {
    asm volatile("cp.async.cg.shared.global [%0], [%1], 16;" :: "r"(saddr), "l"(g));
}
// A-frag half index for element (r, k) of a 128x32 half tile (m16n8k16)
__device__ __forceinline__ int afidx(int r, int k) {
    int ks = k >> 4, kk = k & 15;
    int pair = kk & 1, klane = (kk >> 1) & 3, kh8 = kk >> 3;
    int fg = r >> 4, p = (r >> 3) & 1, rr = r & 7;
    return ((ks * 8 + fg) * 32 + rr * 4 + klane) * 8 + (p + 2 * kh8) * 2 + pair;
}
// B-frag half index for element (k, n) of a 32x128 half tile
__device__ __forceinline__ int bfidx(int k, int n) {
    int ks = k >> 4, kk = k & 15;
    int pair = kk & 1, klane = (kk >> 1) & 3, kh8 = kk >> 3;
    int ng = n >> 3, nn = n & 7;
    return ((ks * 16 + ng) * 32 + nn * 4 + klane) * 4 + kh8 * 2 + pair;
}

// ---------------- prep kernels ---------------------------------------------
__global__ __launch_bounds__(256) void prep_tab(const float* __restrict__ kxs,
                                                const float* __restrict__ kys)
{
    int m = blockIdx.x * 256 + threadIdx.x;
    float s, c;
    float kx = kxs[m], ky = kys[m];
    sincosf(kx, &s, &c);
    float2 S1 = make_float2(c, s);
    float2 S2 = cmulf(S1,S1), S4 = cmulf(S2,S2), S8 = cmulf(S4,S4);
    float2 S16 = cmulf(S8,S8), S32 = cmulf(S16,S16), S64 = cmulf(S32,S32);
    float2 S128 = cmulf(S64,S64);
    float2 T0 = conjf(S128);
    g_S1x[m] = S1; g_S8x[m] = S8;
    float2 q = T0;
#pragma unroll
    for (int j = 0; j < 16; j++) { g_PCH[(size_t)m*16 + j] = conjf(q); q = cmulf(q, S16); }
    float2 p = make_float2(1.f, 0.f);
#pragma unroll
    for (int s8 = 0; s8 < 8; s8++) {
        g_PXU[(size_t)m*16 + s8]     = cmulf(T0, p);
        g_PXU[(size_t)m*16 + 8 + s8] = p;
        p = cmulf(p, S1);
    }
    sincosf(ky, &s, &c);
    S1 = make_float2(c, s);
    S2 = cmulf(S1,S1); S4 = cmulf(S2,S2); S8 = cmulf(S4,S4);
    S16 = cmulf(S8,S8); S32 = cmulf(S16,S16); S64 = cmulf(S32,S32);
    S128 = cmulf(S64,S64);
    g_S1y[m] = S1; g_S8y[m] = S8; g_S64y[m] = S64; g_S128y[m] = S128;
    p = make_float2(1.f, 0.f);
#pragma unroll
    for (int s8 = 0; s8 < 8; s8++) {
        g_PYB[(size_t)m*16 + s8]     = p;
        g_PYB[(size_t)m*16 + 8 + s8] = cmulf(S128, p);
        p = cmulf(p, S1);
    }
}

__global__ __launch_bounds__(256) void prep_bf(const float2* __restrict__ img)
{
    int idx = blockIdx.x * 256 + threadIdx.x;
    int k = idx >> 9, n = idx & 511;
    int v = n & 255, u = k & 255;
    float2 g = img[u * 256 + v];
    float val = (n < 256) ? ((k < 256) ? g.x : -g.y)
                          : ((k < 256) ? g.y :  g.x);
    int nt = n >> 7, nn = n & 127, ch = k >> 5, kk = k & 31;
    g_FB[(nt * 16 + ch) * 4096 + bfidx(kk, nn)] = __float2half_rn(val);
}

__global__ __launch_bounds__(128) void prep_fa()
{
    __shared__ __half tile[4096];
    const int tid = threadIdx.x, gh = tid & 1, grow = tid >> 1;
    const int mtile = blockIdx.x, ch = blockIdx.y;
    const int m0 = mtile * 128;
    const bool iscos = (ch < 8);
    const int j = ((2 * ch) & 15) + gh;
#pragma unroll
    for (int rs = 0; rs < 2; rs++) {
        const int r = grow + 64 * rs, m = m0 + r;
        float2 cur = g_PCH[(size_t)m * 16 + j];
        const float2 st = conjf(g_S1x[m]);
#pragma unroll
        for (int q2 = 0; q2 < 8; q2++) {
            float v0 = iscos ? cur.x : cur.y;  cur = cmulf(cur, st);
            float v1 = iscos ? cur.x : cur.y;  cur = cmulf(cur, st);
            ((__half2*)tile)[afidx(r, 16 * gh + 2 * q2) >> 1] =
                __halves2half2(__float2half_rn(v0), __float2half_rn(v1));
        }
    }
    __syncthreads();
    float4* dst = (float4*)(g_FA + ((size_t)mtile * 16 + ch) * 4096);
    const float4* src = (const float4*)tile;
#pragma unroll
    for (int i = 0; i < 4; i++) dst[i * 128 + tid] = src[i * 128 + tid];
}

__global__ __launch_bounds__(128) void prep_aa()
{
    __shared__ __half tile[4096];
    const int tid = threadIdx.x, gm = tid >> 3, sub = tid & 7;
    const int kst = blockIdx.x, ut = blockIdx.y;
    const int m = kst * 16 + gm;
    float2 cur = g_PXU[(size_t)m * 16 + ut * 8 + sub];
    const float2 stp = g_S8x[m];
    // half2 slot for k'=2gm, 2gm+1 at row u
    const int ks = gm >> 3, klane = gm & 3, kh8 = (gm >> 2) & 1;
#pragma unroll
    for (int q = 0; q < 16; q++) {
        const int u = sub + 8 * q;
        const int fg = u >> 4, p = (u >> 3) & 1, rr = u & 7;
        ((__half2*)tile)[((ks * 8 + fg) * 32 + rr * 4 + klane) * 4 + p + 2 * kh8] =
            __halves2half2(__float2half_rn(cur.x), __float2half_rn(cur.y));
        cur = cmulf(cur, stp);
    }
    __syncthreads();
    float4* dst = (float4*)(g_AA + ((size_t)kst * 2 + ut) * 4096);
    const float4* src = (const float4*)tile;
#pragma unroll
    for (int i = 0; i < 4; i++) dst[i * 128 + tid] = src[i * 128 + tid];
}

// ---------------------------------------------------------------------------
// Forward GEMM (fp16): 128 threads, 4 warps (2 wm x 2 wn), warp tile 64x64,
// both operands cp.async (triple buffer). Fused Ey-reduce + blend -> g_E0.
// ---------------------------------------------------------------------------
__global__ __launch_bounds__(128)
void fwd_gemm(const float2* __restrict__ yrad, const float* __restrict__ lamp,
              const float* __restrict__ kxs, const float* __restrict__ kys)
{
    extern __shared__ __half sh[];
    __half* As = sh;                       // 3 x 4096
    __half* Bs = sh + 12288;               // 3 x 4096
    float2* t_acc = (float2*)(sh + 24576);

    const int tid = threadIdx.x, lane = tid & 31, wid = tid >> 5;
    const int wm = wid >> 1, wn = wid & 1;
    const int mtile = blockIdx.x, m0 = mtile * 128;

    t_acc[tid]       = make_float2(0.f, 0.f);
    t_acc[128 + tid] = make_float2(0.f, 0.f);

    float acc[4][8][4];
#pragma unroll
    for (int i = 0; i < 4; i++)
#pragma unroll
        for (int j = 0; j < 8; j++)
#pragma unroll
            for (int q = 0; q < 4; q++) acc[i][j][q] = 0.f;

#define FWD_FETCH(ls_) do {                                                     \
    if ((ls_) < 64) {                                                           \
        int b_ = (ls_) % 3;                                                     \
        const __half* sA = g_FA + ((size_t)mtile * 16 + ((ls_) & 15)) * 4096;   \
        const __half* sB = g_FB + ((((ls_) >> 4) * 16 + ((ls_) & 15))) * 4096;  \
        uint32_t dA = su32(As + b_ * 4096), dB = su32(Bs + b_ * 4096);          \
        for (int i_ = 0; i_ < 4; i_++) {                                        \
            cp16(dA + (i_ * 128 + tid) * 16, sA + (i_ * 128 + tid) * 8);        \
            cp16(dB + (i_ * 128 + tid) * 16, sB + (i_ * 128 + tid) * 8);        \
        }                                                                       \
    }                                                                           \
    asm volatile("cp.async.commit_group;");                                     \
} while (0)

    FWD_FETCH(0);
    FWD_FETCH(1);
    asm volatile("cp.async.wait_group 1;");
    __syncthreads();

    for (int ls = 0; ls < 64; ls++) {
        const int b = ls % 3, nt = ls >> 4, ch = ls & 15;
        const uint4* Af = (const uint4*)(As + b * 4096);
        const uint2* Bf = (const uint2*)(Bs + b * 4096);
#pragma unroll
        for (int ks = 0; ks < 2; ks++) {
            uint4 av[4];
#pragma unroll
            for (int fm = 0; fm < 4; fm++)
                av[fm] = Af[(ks * 8 + wm * 4 + fm) * 32 + lane];
#pragma unroll
            for (int fn = 0; fn < 8; fn++) {
                uint2 bv = Bf[(ks * 16 + wn * 8 + fn) * 32 + lane];
#pragma unroll
                for (int fm = 0; fm < 4; fm++)
                    mma16(acc[fm][fn], (const uint32_t*)&av[fm], (const uint32_t*)&bv);
            }
        }
        if (ch == 15) {   // fused Ey-weighted reduction for this nt
#pragma unroll
            for (int fm = 0; fm < 4; fm++)
#pragma unroll
            for (int cp = 0; cp < 2; cp++) {
                const int rl = wm * 64 + fm * 16 + cp * 8 + (lane >> 2);
                const int m = m0 + rl;
                const float2 S1c  = conjf(g_S1y[m]);
                const float2 S64c = conjf(g_S64y[m]);
                const float2 EYp  = g_S128y[m];
                const int a2 = ((nt & 1) << 1) | wn;
                float2 S2c = cmulf(S1c, S1c);
                float2 pb = cmulf(cmulf(EYp, cpow4(S64c, a2)), cpow4(S2c, lane & 3));
                float2 S8c = cmulf(S2c, S2c); S8c = cmulf(S8c, S8c);
                float tx = 0.f, ty = 0.f;
#pragma unroll
                for (int fn = 0; fn < 8; fn++) {
                    float v0 = acc[fm][fn][cp * 2 + 0];
                    float v1 = acc[fm][fn][cp * 2 + 1];
                    float2 p1 = cmulf(pb, S1c);
                    if (nt < 2) { tx += v0 * pb.x + v1 * p1.x;  ty += v0 * pb.y + v1 * p1.y; }
                    else        { tx -= v0 * pb.y + v1 * p1.y;  ty += v0 * pb.x + v1 * p1.x; }
                    pb = cmulf(pb, S8c);
                }
                tx += __shfl_xor_sync(0xffffffffu, tx, 1);
                ty += __shfl_xor_sync(0xffffffffu, ty, 1);
                tx += __shfl_xor_sync(0xffffffffu, tx, 2);
                ty += __shfl_xor_sync(0xffffffffu, ty, 2);
                if ((lane & 3) == 0) {
                    t_acc[wn * 128 + rl].x += tx;
                    t_acc[wn * 128 + rl].y += ty;
                }
            }
#pragma unroll
            for (int i = 0; i < 4; i++)
#pragma unroll
                for (int j = 0; j < 8; j++)
#pragma unroll
                    for (int q = 0; q < 4; q++) acc[i][j][q] = 0.f;
        }
        FWD_FETCH(ls + 2);
        asm volatile("cp.async.wait_group 1;");
        __syncthreads();
    }

    {
        const int m = m0 + tid;
        float2 t = make_float2(t_acc[tid].x + t_acc[128 + tid].x,
                               t_acc[tid].y + t_acc[128 + tid].y);
        const float lam = 1.0f / (1.0f + expf(-lamp[0]));
        const float kx = kxs[m], ky = kys[m];
        const float dcf = sqrtf(kx * kx + ky * ky);
        const int sp = m / 640, sam = m - sp * 640;
        const float2 y = yrad[sam * 288 + sp];
        const float w = lam * dcf * ORTHO;
        float2 kdc = make_float2(fmaf(w, t.x, (1.f - lam) * y.x),
                                 fmaf(w, t.y, (1.f - lam) * y.y));
        g_E0[m] = cmulf(kdc, conjf(g_S128y[m]));
    }
}

// ---------------------------------------------------------------------------
// Adjoint GEMM (fp16): 128 threads, warp 64x64. A via cp.async (triple
// buffer), B generated in-loop (double buffer) as half2 pairs.
// ---------------------------------------------------------------------------
__global__ __launch_bounds__(128)
void adj_gemm()
{
    extern __shared__ __half sh[];
    __half* As = sh;            // 3 x 4096
    __half* Bs = sh + 12288;    // 2 x 4096

    const int tid = threadIdx.x, lane = tid & 31, wid = tid >> 5;
    const int wm = wid >> 1, wn = wid & 1;
    const int split = blockIdx.x, ut = blockIdx.y, nt = blockIdx.z;
    const int gm = tid >> 3, sub = tid & 7;
    const bool isRe = (nt < 2);
    const int yb = nt & 1;
    // half2 store slot constants for k'=2gm,2gm+1
    const int bks = gm >> 3, bklane = gm & 3, bkh8 = (gm >> 2) & 1;

    float acc[4][8][4];
#pragma unroll
    for (int i = 0; i < 4; i++)
#pragma unroll
        for (int j = 0; j < 8; j++)
#pragma unroll
            for (int q = 0; q < 4; q++) acc[i][j][q] = 0.f;

#define ADJ_FETCH(st_) do {                                                         \
    if ((st_) < ADJ_ST) {                                                           \
        int b_ = (st_) % 3;                                                         \
        const __half* sA = g_AA + (((size_t)(split * ADJ_ST + (st_)) * 2) + ut) * 4096; \
        uint32_t dA = su32(As + b_ * 4096);                                         \
        for (int i_ = 0; i_ < 4; i_++)                                              \
            cp16(dA + (i_ * 128 + tid) * 16, sA + (i_ * 128 + tid) * 8);            \
    }                                                                               \
    asm volatile("cp.async.commit_group;");                                         \
} while (0)

    float2 tE, tPy, tS8;
#define ADJ_TAB(st_) do {                                                   \
    int m_ = (split * ADJ_ST + (st_)) * 16 + gm;                            \
    tE  = g_E0[m_];                                                         \
    tPy = g_PYB[(size_t)m_ * 16 + yb * 8 + sub];                            \
    tS8 = g_S8y[m_];                                                        \
} while (0)

    // thread covers n0 = sub+16q2, n1 = n0+8 (ng = 2q2, 2q2+1), q2 = 0..7
#define ADJ_GENB(st_) do {                                                  \
    __half2* Bp = (__half2*)(Bs + ((st_) & 1) * 4096);                      \
    float2 s16 = cmulf(tS8, tS8);                                           \
    float2 c0 = cmulf(tE, tPy);                                             \
    float2 c1 = cmulf(c0, tS8);                                             \
    _Pragma("unroll")                                                       \
    for (int q2 = 0; q2 < 8; q2++) {                                        \
        int i0 = ((bks * 16 + 2 * q2) * 32 + sub * 4 + bklane) * 2 + bkh8;  \
        int i1 = i0 + 64;                                                   \
        if (isRe) {                                                         \
            Bp[i0] = __halves2half2(__float2half_rn(c0.x), __float2half_rn(-c0.y)); \
            Bp[i1] = __halves2half2(__float2half_rn(c1.x), __float2half_rn(-c1.y)); \
        } else {                                                            \
            Bp[i0] = __halves2half2(__float2half_rn(c0.y), __float2half_rn(c0.x)); \
            Bp[i1] = __halves2half2(__float2half_rn(c1.y), __float2half_rn(c1.x)); \
        }                                                                   \
        c0 = cmulf(c0, s16);                                                \
        c1 = cmulf(c1, s16);                                                \
    }                                                                       \
} while (0)

    ADJ_FETCH(0);
    ADJ_FETCH(1);
    ADJ_TAB(0); ADJ_GENB(0);
    ADJ_TAB(1);
    asm volatile("cp.async.wait_group 1;");
    __syncthreads();

    for (int st = 0; st < ADJ_ST; st++) {
        if (st + 1 < ADJ_ST) ADJ_GENB(st + 1);
        if (st + 2 < ADJ_ST) ADJ_TAB(st + 2);
        {
            const uint4* Af = (const uint4*)(As + (st % 3) * 4096);
            const uint2* Bf = (const uint2*)(Bs + (st & 1) * 4096);
#pragma unroll
            for (int ks = 0; ks < 2; ks++) {
                uint4 av[4];
#pragma unroll
                for (int fm = 0; fm < 4; fm++)
                    av[fm] = Af[(ks * 8 + wm * 4 + fm) * 32 + lane];
#pragma unroll
                for (int fn = 0; fn < 8; fn++) {
                    uint2 bv = Bf[(ks * 16 + wn * 8 + fn) * 32 + lane];
#pragma unroll
                    for (int fm = 0; fm < 4; fm++)
                        mma16(acc[fm][fn], (const uint32_t*)&av[fm], (const uint32_t*)&bv);
                }
            }
        }
        ADJ_FETCH(st + 2);
        asm volatile("cp.async.wait_group 1;");
        __syncthreads();
    }

    float* outp = g_P + (size_t)((ut * 4 + nt) * NSPLIT + split) * 16384;
#pragma unroll
    for (int fm = 0; fm < 4; fm++)
#pragma unroll
    for (int cp = 0; cp < 2; cp++) {
        const int u = wm * 64 + fm * 16 + cp * 8 + (lane >> 2);
#pragma unroll
        for (int fn = 0; fn < 8; fn++) {
            const int n = wn * 64 + fn * 8 + 2 * (lane & 3);
            *(float2*)&outp[u * 128 + n] =
                make_float2(acc[fm][fn][cp * 2], acc[fm][fn][cp * 2 + 1]);
        }
    }
}

// ---------------------------------------------------------------------------
__global__ __launch_bounds__(256) void reduce_k(float* __restrict__ out)
{
    const int idx = blockIdx.x * 256 + threadIdx.x;
    const int ug = idx >> 9, ng = idx & 511;
    const int ut = ug >> 7, ul = ug & 127, nt = ng >> 7, nl = ng & 127;
    const float* p = g_P + (size_t)((ut * 4 + nt) * NSPLIT) * 16384 + ul * 128 + nl;
    float s = 0.f;
#pragma unroll 8
    for (int sp = 0; sp < NSPLIT; sp++) s += p[(size_t)sp * 16384];
    const int v = ng & 255, c = ng >> 8;
    out[(ug * 256 + v) * 2 + c] = s * ORTHO;
}

// ---------------------------------------------------------------------------
extern "C" void kernel_launch(void* const* d_in, const int* in_sizes, int n_in,
                              void* d_out, int out_size)
{
    const float2* img  = (const float2*)d_in[0];
    const float2* yrad = (const float2*)d_in[1];
    const float*  lamp = (const float*)d_in[2];
    const float*  ktr  = (const float*)d_in[3];
    const float*  kxs  = ktr;
    const float*  kys  = ktr + MTOT;
    float* out = (float*)d_out;

    const int FWD_SMEM = 24576 * 2 + 256 * 8;   // 51200 B
    const int ADJ_SMEM = 20480 * 2;             // 40960 B
    cudaFuncSetAttribute(fwd_gemm, cudaFuncAttributeMaxDynamicSharedMemorySize, FWD_SMEM);
    cudaFuncSetAttribute(adj_gemm, cudaFuncAttributeMaxDynamicSharedMemorySize, ADJ_SMEM);

    prep_tab<<<MTOT/256, 256>>>(kxs, kys);
    prep_bf<<<1024, 256>>>(img);
    prep_fa<<<dim3(NMT, 16), 128>>>();
    prep_aa<<<dim3(NKST, 2), 128>>>();
    fwd_gemm<<<NMT, 128, FWD_SMEM>>>(yrad, lamp, kxs, kys);
    adj_gemm<<<dim3(NSPLIT, 2, 4), 128, ADJ_SMEM>>>();
    reduce_k<<<512, 256>>>(out);
}

// round 16
// speedup vs baseline: 1.8109x; 1.0757x over previous
#include <cuda_runtime.h>
#include <cuda_fp16.h>
#include <math.h>
#include <stdint.h>

#define IM     256
#define MTOT   184320
#define ORTHO  (1.0f/256.0f)
#define NSPLIT 72
#define ADJ_MPER (MTOT/NSPLIT)   // 2560
#define ADJ_ST2  (ADJ_MPER/32)   // 80 stages (32 m = 64 k per stage)
#define NKST     (MTOT/16)       // 11520
#define NMT      (MTOT/128)      // 1440

// ---------------- static scratch -------------------------------------------
__device__ __half  g_FB[4*16*4096];                 // fwd B frag tiles (512 KB)
__device__ __half  g_FA[(size_t)NMT*16*4096];       // fwd A frag tiles (188 MB)
__device__ __half  g_AA[(size_t)NKST*2*4096];       // adj A frag tiles (188 MB)
__device__ float2 g_S1x[MTOT], g_S8x[MTOT];
__device__ float2 g_S1y[MTOT], g_S8y[MTOT], g_S64y[MTOT], g_S128y[MTOT];
__device__ float2 g_PCH[(size_t)MTOT*16];           // conj(T0x*S16x^j)
__device__ float2 g_PXU[(size_t)MTOT*16];           // ut0: T0x*S1x^s ; ut1: S1x^s
__device__ float2 g_PYB[(size_t)MTOT*16];           // b0: S1y^s ; b1: S128y*S1y^s
__device__ float2 g_E0[MTOT];
__device__ float  g_P[(size_t)8*NSPLIT*128*128];    // adjoint partials

// ---------------- helpers --------------------------------------------------
__device__ __forceinline__ float2 cmulf(float2 a, float2 b) {
    return make_float2(a.x*b.x - a.y*b.y, a.x*b.y + a.y*b.x);
}
__device__ __forceinline__ float2 conjf(float2 a) { return make_float2(a.x, -a.y); }
__device__ __forceinline__ float2 cpow4(float2 b, int e) {
    float2 r = make_float2(1.f, 0.f);
#pragma unroll
    for (int i = 0; i < 4; i++) { if (e & (1 << i)) r = cmulf(r, b); b = cmulf(b, b); }
    return r;
}
__device__ __forceinline__ void mma16(float* d, const uint32_t* a, const uint32_t* b) {
    asm volatile(
        "mma.sync.aligned.m16n8k16.row.col.f32.f16.f16.f32 "
        "{%0,%1,%2,%3}, {%4,%5,%6,%7}, {%8,%9}, {%0,%1,%2,%3};"
        : "+f"(d[0]), "+f"(d[1]), "+f"(d[2]), "+f"(d[3])
        : "r"(a[0]), "r"(a[1]), "r"(a[2]), "r"(a[3]), "r"(b[0]), "r"(b[1]));
}
__device__ __forceinline__ uint32_t su32(const void* p) {
    uint32_t a; asm("{ .reg .u64 t; cvta.to.shared.u64 t, %1; cvt.u32.u64 %0, t; }" : "=r"(a) : "l"(p));
    return a;
}
__device__ __forceinline__ void cp16(uint32_t saddr, const void* g) {
    asm volatile("cp.async.cg.shared.global [%0], [%1], 16;" :: "r"(saddr), "l"(g));
}
// A-frag half index for element (r, k) of a 128x32 half tile (m16n8k16)
__device__ __forceinline__ int afidx(int r, int k) {
    int ks = k >> 4, kk = k & 15;
    int pair = kk & 1, klane = (kk >> 1) & 3, kh8 = kk >> 3;
    int fg = r >> 4, p = (r >> 3) & 1, rr = r & 7;
    return ((ks * 8 + fg) * 32 + rr * 4 + klane) * 8 + (p + 2 * kh8) * 2 + pair;
}
// B-frag half index for element (k, n) of a 32x128 half tile
__device__ __forceinline__ int bfidx(int k, int n) {
    int ks = k >> 4, kk = k & 15;
    int pair = kk & 1, klane = (kk >> 1) & 3, kh8 = kk >> 3;
    int ng = n >> 3, nn = n & 7;
    return ((ks * 16 + ng) * 32 + nn * 4 + klane) * 4 + kh8 * 2 + pair;
}

// ---------------- prep kernels ---------------------------------------------
__global__ __launch_bounds__(256) void prep_tab(const float* __restrict__ kxs,
                                                const float* __restrict__ kys)
{
    int m = blockIdx.x * 256 + threadIdx.x;
    float s, c;
    float kx = kxs[m], ky = kys[m];
    sincosf(kx, &s, &c);
    float2 S1 = make_float2(c, s);
    float2 S2 = cmulf(S1,S1), S4 = cmulf(S2,S2), S8 = cmulf(S4,S4);
    float2 S16 = cmulf(S8,S8), S32 = cmulf(S16,S16), S64 = cmulf(S32,S32);
    float2 S128 = cmulf(S64,S64);
    float2 T0 = conjf(S128);
    g_S1x[m] = S1; g_S8x[m] = S8;
    float2 q = T0;
#pragma unroll
    for (int j = 0; j < 16; j++) { g_PCH[(size_t)m*16 + j] = conjf(q); q = cmulf(q, S16); }
    float2 p = make_float2(1.f, 0.f);
#pragma unroll
    for (int s8 = 0; s8 < 8; s8++) {
        g_PXU[(size_t)m*16 + s8]     = cmulf(T0, p);
        g_PXU[(size_t)m*16 + 8 + s8] = p;
        p = cmulf(p, S1);
    }
    sincosf(ky, &s, &c);
    S1 = make_float2(c, s);
    S2 = cmulf(S1,S1); S4 = cmulf(S2,S2); S8 = cmulf(S4,S4);
    S16 = cmulf(S8,S8); S32 = cmulf(S16,S16); S64 = cmulf(S32,S32);
    S128 = cmulf(S64,S64);
    g_S1y[m] = S1; g_S8y[m] = S8; g_S64y[m] = S64; g_S128y[m] = S128;
    p = make_float2(1.f, 0.f);
#pragma unroll
    for (int s8 = 0; s8 < 8; s8++) {
        g_PYB[(size_t)m*16 + s8]     = p;
        g_PYB[(size_t)m*16 + 8 + s8] = cmulf(S128, p);
        p = cmulf(p, S1);
    }
}

__global__ __launch_bounds__(256) void prep_bf(const float2* __restrict__ img)
{
    int idx = blockIdx.x * 256 + threadIdx.x;
    int k = idx >> 9, n = idx & 511;
    int v = n & 255, u = k & 255;
    float2 g = img[u * 256 + v];
    float val = (n < 256) ? ((k < 256) ? g.x : -g.y)
                          : ((k < 256) ? g.y :  g.x);
    int nt = n >> 7, nn = n & 127, ch = k >> 5, kk = k & 31;
    g_FB[(nt * 16 + ch) * 4096 + bfidx(kk, nn)] = __float2half_rn(val);
}

__global__ __launch_bounds__(128) void prep_fa()
{
    __shared__ __half tile[4096];
    const int tid = threadIdx.x, gh = tid & 1, grow = tid >> 1;
    const int mtile = blockIdx.x, ch = blockIdx.y;
    const int m0 = mtile * 128;
    const bool iscos = (ch < 8);
    const int j = ((2 * ch) & 15) + gh;
#pragma unroll
    for (int rs = 0; rs < 2; rs++) {
        const int r = grow + 64 * rs, m = m0 + r;
        float2 cur = g_PCH[(size_t)m * 16 + j];
        const float2 st = conjf(g_S1x[m]);
#pragma unroll
        for (int q2 = 0; q2 < 8; q2++) {
            float v0 = iscos ? cur.x : cur.y;  cur = cmulf(cur, st);
            float v1 = iscos ? cur.x : cur.y;  cur = cmulf(cur, st);
            ((__half2*)tile)[afidx(r, 16 * gh + 2 * q2) >> 1] =
                __halves2half2(__float2half_rn(v0), __float2half_rn(v1));
        }
    }
    __syncthreads();
    float4* dst = (float4*)(g_FA + ((size_t)mtile * 16 + ch) * 4096);
    const float4* src = (const float4*)tile;
#pragma unroll
    for (int i = 0; i < 4; i++) dst[i * 128 + tid] = src[i * 128 + tid];
}

__global__ __launch_bounds__(128) void prep_aa()
{
    __shared__ __half tile[4096];
    const int tid = threadIdx.x, gm = tid >> 3, sub = tid & 7;
    const int kst = blockIdx.x, ut = blockIdx.y;
    const int m = kst * 16 + gm;
    float2 cur = g_PXU[(size_t)m * 16 + ut * 8 + sub];
    const float2 stp = g_S8x[m];
    const int ks = gm >> 3, klane = gm & 3, kh8 = (gm >> 2) & 1;
#pragma unroll
    for (int q = 0; q < 16; q++) {
        const int u = sub + 8 * q;
        const int fg = u >> 4, p = (u >> 3) & 1, rr = u & 7;
        ((__half2*)tile)[((ks * 8 + fg) * 32 + rr * 4 + klane) * 4 + p + 2 * kh8] =
            __halves2half2(__float2half_rn(cur.x), __float2half_rn(cur.y));
        cur = cmulf(cur, stp);
    }
    __syncthreads();
    float4* dst = (float4*)(g_AA + ((size_t)kst * 2 + ut) * 4096);
    const float4* src = (const float4*)tile;
#pragma unroll
    for (int i = 0; i < 4; i++) dst[i * 128 + tid] = src[i * 128 + tid];
}

// ---------------------------------------------------------------------------
// Forward GEMM (fp16, K=64 stages): 128 threads, warp 64x64, double buffer.
// 32 stages; nt boundary every 8. Fused Ey-reduce + blend -> g_E0.
// ---------------------------------------------------------------------------
__global__ __launch_bounds__(128)
void fwd_gemm(const float2* __restrict__ yrad, const float* __restrict__ lamp,
              const float* __restrict__ kxs, const float* __restrict__ kys)
{
    extern __shared__ __half sh[];
    __half* As = sh;                       // 2 x 8192
    __half* Bs = sh + 16384;               // 2 x 8192
    float2* t_acc = (float2*)(sh + 32768);

    const int tid = threadIdx.x, lane = tid & 31, wid = tid >> 5;
    const int wm = wid >> 1, wn = wid & 1;
    const int mtile = blockIdx.x, m0 = mtile * 128;

    t_acc[tid]       = make_float2(0.f, 0.f);
    t_acc[128 + tid] = make_float2(0.f, 0.f);

    float acc[4][8][4];
#pragma unroll
    for (int i = 0; i < 4; i++)
#pragma unroll
        for (int j = 0; j < 8; j++)
#pragma unroll
            for (int q = 0; q < 4; q++) acc[i][j][q] = 0.f;

#define FWD_FETCH(ls_) do {                                                     \
    if ((ls_) < 32) {                                                           \
        int b_ = (ls_) & 1;                                                     \
        const __half* sA = g_FA + ((size_t)mtile * 16 + 2 * ((ls_) & 7)) * 4096;  \
        const __half* sB = g_FB + ((((ls_) >> 3) * 16 + 2 * ((ls_) & 7))) * 4096; \
        uint32_t dA = su32(As + b_ * 8192), dB = su32(Bs + b_ * 8192);          \
        for (int i_ = 0; i_ < 8; i_++) {                                        \
            cp16(dA + (i_ * 128 + tid) * 16, sA + (i_ * 128 + tid) * 8);        \
            cp16(dB + (i_ * 128 + tid) * 16, sB + (i_ * 128 + tid) * 8);        \
        }                                                                       \
    }                                                                           \
    asm volatile("cp.async.commit_group;");                                     \
} while (0)

    FWD_FETCH(0);
    asm volatile("cp.async.wait_group 0;");
    __syncthreads();

    for (int ls = 0; ls < 32; ls++) {
        const int b = ls & 1, nt = ls >> 3, c8 = ls & 7;
        FWD_FETCH(ls + 1);
        const uint4* Af = (const uint4*)(As + b * 8192);
        const uint2* Bf = (const uint2*)(Bs + b * 8192);
#pragma unroll
        for (int ck = 0; ck < 2; ck++) {
#pragma unroll
            for (int ks = 0; ks < 2; ks++) {
                uint4 av[4];
#pragma unroll
                for (int fm = 0; fm < 4; fm++)
                    av[fm] = Af[ck * 512 + (ks * 8 + wm * 4 + fm) * 32 + lane];
#pragma unroll
                for (int fn = 0; fn < 8; fn++) {
                    uint2 bv = Bf[ck * 1024 + (ks * 16 + wn * 8 + fn) * 32 + lane];
#pragma unroll
                    for (int fm = 0; fm < 4; fm++)
                        mma16(acc[fm][fn], (const uint32_t*)&av[fm], (const uint32_t*)&bv);
                }
            }
        }
        if (c8 == 7) {   // fused Ey-weighted reduction for this nt
#pragma unroll
            for (int fm = 0; fm < 4; fm++)
#pragma unroll
            for (int cp = 0; cp < 2; cp++) {
                const int rl = wm * 64 + fm * 16 + cp * 8 + (lane >> 2);
                const int m = m0 + rl;
                const float2 S1c  = conjf(g_S1y[m]);
                const float2 S64c = conjf(g_S64y[m]);
                const float2 EYp  = g_S128y[m];
                const int a2 = ((nt & 1) << 1) | wn;
                float2 S2c = cmulf(S1c, S1c);
                float2 pb = cmulf(cmulf(EYp, cpow4(S64c, a2)), cpow4(S2c, lane & 3));
                float2 S8c = cmulf(S2c, S2c); S8c = cmulf(S8c, S8c);
                float tx = 0.f, ty = 0.f;
#pragma unroll
                for (int fn = 0; fn < 8; fn++) {
                    float v0 = acc[fm][fn][cp * 2 + 0];
                    float v1 = acc[fm][fn][cp * 2 + 1];
                    float2 p1 = cmulf(pb, S1c);
                    if (nt < 2) { tx += v0 * pb.x + v1 * p1.x;  ty += v0 * pb.y + v1 * p1.y; }
                    else        { tx -= v0 * pb.y + v1 * p1.y;  ty += v0 * pb.x + v1 * p1.x; }
                    pb = cmulf(pb, S8c);
                }
                tx += __shfl_xor_sync(0xffffffffu, tx, 1);
                ty += __shfl_xor_sync(0xffffffffu, ty, 1);
                tx += __shfl_xor_sync(0xffffffffu, tx, 2);
                ty += __shfl_xor_sync(0xffffffffu, ty, 2);
                if ((lane & 3) == 0) {
                    t_acc[wn * 128 + rl].x += tx;
                    t_acc[wn * 128 + rl].y += ty;
                }
            }
#pragma unroll
            for (int i = 0; i < 4; i++)
#pragma unroll
                for (int j = 0; j < 8; j++)
#pragma unroll
                    for (int q = 0; q < 4; q++) acc[i][j][q] = 0.f;
        }
        asm volatile("cp.async.wait_group 0;");
        __syncthreads();
    }

    {
        const int m = m0 + tid;
        float2 t = make_float2(t_acc[tid].x + t_acc[128 + tid].x,
                               t_acc[tid].y + t_acc[128 + tid].y);
        const float lam = 1.0f / (1.0f + expf(-lamp[0]));
        const float kx = kxs[m], ky = kys[m];
        const float dcf = sqrtf(kx * kx + ky * ky);
        const int sp = m / 640, sam = m - sp * 640;
        const float2 y = yrad[sam * 288 + sp];
        const float w = lam * dcf * ORTHO;
        float2 kdc = make_float2(fmaf(w, t.x, (1.f - lam) * y.x),
                                 fmaf(w, t.y, (1.f - lam) * y.y));
        g_E0[m] = cmulf(kdc, conjf(g_S128y[m]));
    }
}

// ---------------------------------------------------------------------------
// Adjoint GEMM (fp16, K=64 stages = 32 m): 128 threads, warp 64x64,
// double buffer; A cp.async, B generated (two 16-m sub-chunks per stage).
// ---------------------------------------------------------------------------
__global__ __launch_bounds__(128)
void adj_gemm()
{
    extern __shared__ __half sh[];
    __half* As = sh;            // 2 x 8192
    __half* Bs = sh + 16384;    // 2 x 8192

    const int tid = threadIdx.x, lane = tid & 31, wid = tid >> 5;
    const int wm = wid >> 1, wn = wid & 1;
    const int split = blockIdx.x, ut = blockIdx.y, nt = blockIdx.z;
    const int gm = tid >> 3, sub = tid & 7;
    const bool isRe = (nt < 2);
    const int yb = nt & 1;
    const int bks = gm >> 3, bklane = gm & 3, bkh8 = (gm >> 2) & 1;

    float acc[4][8][4];
#pragma unroll
    for (int i = 0; i < 4; i++)
#pragma unroll
        for (int j = 0; j < 8; j++)
#pragma unroll
            for (int q = 0; q < 4; q++) acc[i][j][q] = 0.f;

#define ADJ_FETCH(st_) do {                                                         \
    if ((st_) < ADJ_ST2) {                                                          \
        int b_ = (st_) & 1;                                                         \
        const __half* sA = g_AA + (((size_t)(split * (2*ADJ_ST2) + 2*(st_)) * 2) + ut) * 4096; \
        uint32_t dA = su32(As + b_ * 8192);                                         \
        for (int i_ = 0; i_ < 4; i_++) {                                            \
            cp16(dA + (i_ * 128 + tid) * 16, sA + (i_ * 128 + tid) * 8);            \
            cp16(dA + 8192 + (i_ * 128 + tid) * 16, sA + 8192 + (i_ * 128 + tid) * 8); \
        }                                                                           \
    }                                                                               \
    asm volatile("cp.async.commit_group;");                                         \
} while (0)

    float2 tE[2], tPy[2], tS8[2];
#define ADJ_TAB(st_) do {                                                   \
    _Pragma("unroll")                                                       \
    for (int c_ = 0; c_ < 2; c_++) {                                        \
        int m_ = (split * (2*ADJ_ST2) + 2*(st_) + c_) * 16 + gm;            \
        tE[c_]  = g_E0[m_];                                                 \
        tPy[c_] = g_PYB[(size_t)m_ * 16 + yb * 8 + sub];                    \
        tS8[c_] = g_S8y[m_];                                                \
    }                                                                       \
} while (0)

#define ADJ_GENB(st_) do {                                                  \
    __half2* Bp = (__half2*)(Bs + ((st_) & 1) * 8192);                      \
    _Pragma("unroll")                                                       \
    for (int c_ = 0; c_ < 2; c_++) {                                        \
        float2 s16 = cmulf(tS8[c_], tS8[c_]);                               \
        float2 c0 = cmulf(tE[c_], tPy[c_]);                                 \
        float2 c1 = cmulf(c0, tS8[c_]);                                     \
        _Pragma("unroll")                                                   \
        for (int q2 = 0; q2 < 8; q2++) {                                    \
            int i0 = c_ * 2048 + ((bks * 16 + 2 * q2) * 32 + sub * 4 + bklane) * 2 + bkh8; \
            int i1 = i0 + 64;                                               \
            if (isRe) {                                                     \
                Bp[i0] = __halves2half2(__float2half_rn(c0.x), __float2half_rn(-c0.y)); \
                Bp[i1] = __halves2half2(__float2half_rn(c1.x), __float2half_rn(-c1.y)); \
            } else {                                                        \
                Bp[i0] = __halves2half2(__float2half_rn(c0.y), __float2half_rn(c0.x)); \
                Bp[i1] = __halves2half2(__float2half_rn(c1.y), __float2half_rn(c1.x)); \
            }                                                               \
            c0 = cmulf(c0, s16);                                            \
            c1 = cmulf(c1, s16);                                            \
        }                                                                   \
    }                                                                       \
} while (0)

    ADJ_FETCH(0);
    ADJ_TAB(0); ADJ_GENB(0);
    ADJ_TAB(1);
    asm volatile("cp.async.wait_group 0;");
    __syncthreads();

    for (int st = 0; st < ADJ_ST2; st++) {
        ADJ_FETCH(st + 1);
        if (st + 1 < ADJ_ST2) ADJ_GENB(st + 1);
        if (st + 2 < ADJ_ST2) ADJ_TAB(st + 2);
        {
            const uint4* Af = (const uint4*)(As + (st & 1) * 8192);
            const uint2* Bf = (const uint2*)(Bs + (st & 1) * 8192);
#pragma unroll
            for (int ck = 0; ck < 2; ck++) {
#pragma unroll
                for (int ks = 0; ks < 2; ks++) {
                    uint4 av[4];
#pragma unroll
                    for (int fm = 0; fm < 4; fm++)
                        av[fm] = Af[ck * 512 + (ks * 8 + wm * 4 + fm) * 32 + lane];
#pragma unroll
                    for (int fn = 0; fn < 8; fn++) {
                        uint2 bv = Bf[ck * 1024 + (ks * 16 + wn * 8 + fn) * 32 + lane];
#pragma unroll
                        for (int fm = 0; fm < 4; fm++)
                            mma16(acc[fm][fn], (const uint32_t*)&av[fm], (const uint32_t*)&bv);
                    }
                }
            }
        }
        asm volatile("cp.async.wait_group 0;");
        __syncthreads();
    }

    float* outp = g_P + (size_t)((ut * 4 + nt) * NSPLIT + split) * 16384;
#pragma unroll
    for (int fm = 0; fm < 4; fm++)
#pragma unroll
    for (int cp = 0; cp < 2; cp++) {
        const int u = wm * 64 + fm * 16 + cp * 8 + (lane >> 2);
#pragma unroll
        for (int fn = 0; fn < 8; fn++) {
            const int n = wn * 64 + fn * 8 + 2 * (lane & 3);
            *(float2*)&outp[u * 128 + n] =
                make_float2(acc[fm][fn][cp * 2], acc[fm][fn][cp * 2 + 1]);
        }
    }
}

// ---------------------------------------------------------------------------
__global__ __launch_bounds__(256) void reduce_k(float* __restrict__ out)
{
    const int idx = blockIdx.x * 256 + threadIdx.x;
    const int ug = idx >> 9, ng = idx & 511;
    const int ut = ug >> 7, ul = ug & 127, nt = ng >> 7, nl = ng & 127;
    const float* p = g_P + (size_t)((ut * 4 + nt) * NSPLIT) * 16384 + ul * 128 + nl;
    float s = 0.f;
#pragma unroll 8
    for (int sp = 0; sp < NSPLIT; sp++) s += p[(size_t)sp * 16384];
    const int v = ng & 255, c = ng >> 8;
    out[(ug * 256 + v) * 2 + c] = s * ORTHO;
}

// ---------------------------------------------------------------------------
extern "C" void kernel_launch(void* const* d_in, const int* in_sizes, int n_in,
                              void* d_out, int out_size)
{
    const float2* img  = (const float2*)d_in[0];
    const float2* yrad = (const float2*)d_in[1];
    const float*  lamp = (const float*)d_in[2];
    const float*  ktr  = (const float*)d_in[3];
    const float*  kxs  = ktr;
    const float*  kys  = ktr + MTOT;
    float* out = (float*)d_out;

    const int FWD_SMEM = 32768 * 2 + 256 * 8;   // 67584 B
    const int ADJ_SMEM = 32768 * 2;             // 65536 B
    cudaFuncSetAttribute(fwd_gemm, cudaFuncAttributeMaxDynamicSharedMemorySize, FWD_SMEM);
    cudaFuncSetAttribute(adj_gemm, cudaFuncAttributeMaxDynamicSharedMemorySize, ADJ_SMEM);

    prep_tab<<<MTOT/256, 256>>>(kxs, kys);
    prep_bf<<<1024, 256>>>(img);
    prep_fa<<<dim3(NMT, 16), 128>>>();
    prep_aa<<<dim3(NKST, 2), 128>>>();
    fwd_gemm<<<NMT, 128, FWD_SMEM>>>(yrad, lamp, kxs, kys);
    adj_gemm<<<dim3(NSPLIT, 2, 4), 128, ADJ_SMEM>>>();
    reduce_k<<<512, 256>>>(out);
}

// round 17
// speedup vs baseline: 2.1968x; 1.2131x over previous
#include <cuda_runtime.h>
#include <cuda_fp16.h>
#include <math.h>
#include <stdint.h>

#define IM     256
#define MTOT   184320
#define ORTHO  (1.0f/256.0f)
#define NSPLIT 72
#define NREP   92160             // 288 spokes x 320 reps
#define ADJ_ST3 40               // stages per split (32 reps = 64 K each)
#define NKSTA  (NREP/16)         // 5760 rep A-tiles
#define NMT    (MTOT/128)        // 1440

// ---------------- static scratch -------------------------------------------
__device__ __half  g_FB[4*16*4096];                 // fwd B frag tiles
__device__ __half  g_FA[(size_t)NMT*16*4096];       // fwd A frag tiles (188 MB)
__device__ __half  g_AA[(size_t)NKSTA*2*4096];      // adj rep A frag tiles (94 MB)
__device__ float2 g_S1x[MTOT], g_S8x[MTOT];
__device__ float2 g_S1y[MTOT], g_S8y[MTOT], g_S64y[MTOT], g_S128y[MTOT];
__device__ float2 g_PCH[(size_t)MTOT*16];
__device__ float2 g_PXU[(size_t)MTOT*16];
__device__ float2 g_PYB[(size_t)MTOT*16];
__device__ float2 g_E0[MTOT];
__device__ float2 g_corr[1];
__device__ float  g_P[(size_t)8*NSPLIT*128*128];

// ---------------- helpers --------------------------------------------------
__device__ __forceinline__ float2 cmulf(float2 a, float2 b) {
    return make_float2(a.x*b.x - a.y*b.y, a.x*b.y + a.y*b.x);
}
__device__ __forceinline__ float2 conjf(float2 a) { return make_float2(a.x, -a.y); }
__device__ __forceinline__ float2 cpow4(float2 b, int e) {
    float2 r = make_float2(1.f, 0.f);
#pragma unroll
    for (int i = 0; i < 4; i++) { if (e & (1 << i)) r = cmulf(r, b); b = cmulf(b, b); }
    return r;
}
__device__ __forceinline__ void mma16(float* d, const uint32_t* a, const uint32_t* b) {
    asm volatile(
        "mma.sync.aligned.m16n8k16.row.col.f32.f16.f16.f32 "
        "{%0,%1,%2,%3}, {%4,%5,%6,%7}, {%8,%9}, {%0,%1,%2,%3};"
        : "+f"(d[0]), "+f"(d[1]), "+f"(d[2]), "+f"(d[3])
        : "r"(a[0]), "r"(a[1]), "r"(a[2]), "r"(a[3]), "r"(b[0]), "r"(b[1]));
}
__device__ __forceinline__ uint32_t su32(const void* p) {
    uint32_t a; asm("{ .reg .u64 t; cvta.to.shared.u64 t, %1; cvt.u32.u64 %0, t; }" : "=r"(a) : "l"(p));
    return a;
}
__device__ __forceinline__ void cp16(uint32_t saddr, const void* g) {
    asm volatile("cp.async.cg.shared.global [%0], [%1], 16;" :: "r"(saddr), "l"(g));
}
__device__ __forceinline__ int afidx(int r, int k) {
    int ks = k >> 4, kk = k & 15;
    int pair = kk & 1, klane = (kk >> 1) & 3, kh8 = kk >> 3;
    int fg = r >> 4, p = (r >> 3) & 1, rr = r & 7;
    return ((ks * 8 + fg) * 32 + rr * 4 + klane) * 8 + (p + 2 * kh8) * 2 + pair;
}
__device__ __forceinline__ int bfidx(int k, int n) {
    int ks = k >> 4, kk = k & 15;
    int pair = kk & 1, klane = (kk >> 1) & 3, kh8 = kk >> 3;
    int ng = n >> 3, nn = n & 7;
    return ((ks * 16 + ng) * 32 + nn * 4 + klane) * 4 + kh8 * 2 + pair;
}

// ---------------- prep kernels ---------------------------------------------
__global__ __launch_bounds__(256) void prep_tab(const float* __restrict__ kxs,
                                                const float* __restrict__ kys)
{
    int m = blockIdx.x * 256 + threadIdx.x;
    float s, c;
    float kx = kxs[m], ky = kys[m];
    sincosf(kx, &s, &c);
    float2 S1 = make_float2(c, s);
    float2 S2 = cmulf(S1,S1), S4 = cmulf(S2,S2), S8 = cmulf(S4,S4);
    float2 S16 = cmulf(S8,S8), S32 = cmulf(S16,S16), S64 = cmulf(S32,S32);
    float2 S128 = cmulf(S64,S64);
    float2 T0 = conjf(S128);
    g_S1x[m] = S1; g_S8x[m] = S8;
    float2 q = T0;
#pragma unroll
    for (int j = 0; j < 16; j++) { g_PCH[(size_t)m*16 + j] = conjf(q); q = cmulf(q, S16); }
    float2 p = make_float2(1.f, 0.f);
#pragma unroll
    for (int s8 = 0; s8 < 8; s8++) {
        g_PXU[(size_t)m*16 + s8]     = cmulf(T0, p);
        g_PXU[(size_t)m*16 + 8 + s8] = p;
        p = cmulf(p, S1);
    }
    sincosf(ky, &s, &c);
    S1 = make_float2(c, s);
    S2 = cmulf(S1,S1); S4 = cmulf(S2,S2); S8 = cmulf(S4,S4);
    S16 = cmulf(S8,S8); S32 = cmulf(S16,S16); S64 = cmulf(S32,S32);
    S128 = cmulf(S64,S64);
    g_S1y[m] = S1; g_S8y[m] = S8; g_S64y[m] = S64; g_S128y[m] = S128;
    p = make_float2(1.f, 0.f);
#pragma unroll
    for (int s8 = 0; s8 < 8; s8++) {
        g_PYB[(size_t)m*16 + s8]     = p;
        g_PYB[(size_t)m*16 + 8 + s8] = cmulf(S128, p);
        p = cmulf(p, S1);
    }
}

__global__ __launch_bounds__(256) void prep_bf(const float2* __restrict__ img)
{
    int idx = blockIdx.x * 256 + threadIdx.x;
    int k = idx >> 9, n = idx & 511;
    int v = n & 255, u = k & 255;
    float2 g = img[u * 256 + v];
    float val = (n < 256) ? ((k < 256) ? g.x : -g.y)
                          : ((k < 256) ? g.y :  g.x);
    int nt = n >> 7, nn = n & 127, ch = k >> 5, kk = k & 31;
    g_FB[(nt * 16 + ch) * 4096 + bfidx(kk, nn)] = __float2half_rn(val);
}

__global__ __launch_bounds__(128) void prep_fa()
{
    __shared__ __half tile[4096];
    const int tid = threadIdx.x, gh = tid & 1, grow = tid >> 1;
    const int mtile = blockIdx.x, ch = blockIdx.y;
    const int m0 = mtile * 128;
    const bool iscos = (ch < 8);
    const int j = ((2 * ch) & 15) + gh;
#pragma unroll
    for (int rs = 0; rs < 2; rs++) {
        const int r = grow + 64 * rs, m = m0 + r;
        float2 cur = g_PCH[(size_t)m * 16 + j];
        const float2 st = conjf(g_S1x[m]);
#pragma unroll
        for (int q2 = 0; q2 < 8; q2++) {
            float v0 = iscos ? cur.x : cur.y;  cur = cmulf(cur, st);
            float v1 = iscos ? cur.x : cur.y;  cur = cmulf(cur, st);
            ((__half2*)tile)[afidx(r, 16 * gh + 2 * q2) >> 1] =
                __halves2half2(__float2half_rn(v0), __float2half_rn(v1));
        }
    }
    __syncthreads();
    float4* dst = (float4*)(g_FA + ((size_t)mtile * 16 + ch) * 4096);
    const float4* src = (const float4*)tile;
#pragma unroll
    for (int i = 0; i < 4; i++) dst[i * 128 + tid] = src[i * 128 + tid];
}

// adj rep A-tiles: rep rm -> m = rm + 320*(rm/320)  (spoke sp, sam r<320)
__global__ __launch_bounds__(128) void prep_aa()
{
    __shared__ __half tile[4096];
    const int tid = threadIdx.x, gm = tid >> 3, sub = tid & 7;
    const int kst = blockIdx.x, ut = blockIdx.y;
    const int rm = kst * 16 + gm;
    const int sp = rm / 320;
    const int m = rm + sp * 320;
    float2 cur = g_PXU[(size_t)m * 16 + ut * 8 + sub];
    const float2 stp = g_S8x[m];
    const int ks = gm >> 3, klane = gm & 3, kh8 = (gm >> 2) & 1;
#pragma unroll
    for (int q = 0; q < 16; q++) {
        const int u = sub + 8 * q;
        const int fg = u >> 4, p = (u >> 3) & 1, rr = u & 7;
        ((__half2*)tile)[((ks * 8 + fg) * 32 + rr * 4 + klane) * 4 + p + 2 * kh8] =
            __halves2half2(__float2half_rn(cur.x), __float2half_rn(cur.y));
        cur = cmulf(cur, stp);
    }
    __syncthreads();
    float4* dst = (float4*)(g_AA + ((size_t)kst * 2 + ut) * 4096);
    const float4* src = (const float4*)tile;
#pragma unroll
    for (int i = 0; i < 4; i++) dst[i * 128 + tid] = src[i * 128 + tid];
}

// corr = sum over spokes of kdc at sam=320 (k=0 -> E0 = kdc); added to all pixels
__global__ __launch_bounds__(512) void corr_k()
{
    __shared__ float2 red[16];
    const int tid = threadIdx.x;
    float2 v = make_float2(0.f, 0.f);
    if (tid < 288) v = g_E0[tid * 640 + 320];
#pragma unroll
    for (int o = 16; o > 0; o >>= 1) {
        v.x += __shfl_xor_sync(0xffffffffu, v.x, o);
        v.y += __shfl_xor_sync(0xffffffffu, v.y, o);
    }
    if ((tid & 31) == 0) red[tid >> 5] = v;
    __syncthreads();
    if (tid == 0) {
        float2 s = make_float2(0.f, 0.f);
#pragma unroll
        for (int i = 0; i < 16; i++) { s.x += red[i].x; s.y += red[i].y; }
        g_corr[0] = s;
    }
}

// ---------------------------------------------------------------------------
// Forward GEMM (unchanged from round 16)
// ---------------------------------------------------------------------------
__global__ __launch_bounds__(128)
void fwd_gemm(const float2* __restrict__ yrad, const float* __restrict__ lamp,
              const float* __restrict__ kxs, const float* __restrict__ kys)
{
    extern __shared__ __half sh[];
    __half* As = sh;
    __half* Bs = sh + 16384;
    float2* t_acc = (float2*)(sh + 32768);

    const int tid = threadIdx.x, lane = tid & 31, wid = tid >> 5;
    const int wm = wid >> 1, wn = wid & 1;
    const int mtile = blockIdx.x, m0 = mtile * 128;

    t_acc[tid]       = make_float2(0.f, 0.f);
    t_acc[128 + tid] = make_float2(0.f, 0.f);

    float acc[4][8][4];
#pragma unroll
    for (int i = 0; i < 4; i++)
#pragma unroll
        for (int j = 0; j < 8; j++)
#pragma unroll
            for (int q = 0; q < 4; q++) acc[i][j][q] = 0.f;

#define FWD_FETCH(ls_) do {                                                     \
    if ((ls_) < 32) {                                                           \
        int b_ = (ls_) & 1;                                                     \
        const __half* sA = g_FA + ((size_t)mtile * 16 + 2 * ((ls_) & 7)) * 4096;  \
        const __half* sB = g_FB + ((((ls_) >> 3) * 16 + 2 * ((ls_) & 7))) * 4096; \
        uint32_t dA = su32(As + b_ * 8192), dB = su32(Bs + b_ * 8192);          \
        for (int i_ = 0; i_ < 8; i_++) {                                        \
            cp16(dA + (i_ * 128 + tid) * 16, sA + (i_ * 128 + tid) * 8);        \
            cp16(dB + (i_ * 128 + tid) * 16, sB + (i_ * 128 + tid) * 8);        \
        }                                                                       \
    }                                                                           \
    asm volatile("cp.async.commit_group;");                                     \
} while (0)

    FWD_FETCH(0);
    asm volatile("cp.async.wait_group 0;");
    __syncthreads();

    for (int ls = 0; ls < 32; ls++) {
        const int b = ls & 1, nt = ls >> 3, c8 = ls & 7;
        FWD_FETCH(ls + 1);
        const uint4* Af = (const uint4*)(As + b * 8192);
        const uint2* Bf = (const uint2*)(Bs + b * 8192);
#pragma unroll
        for (int ck = 0; ck < 2; ck++) {
#pragma unroll
            for (int ks = 0; ks < 2; ks++) {
                uint4 av[4];
#pragma unroll
                for (int fm = 0; fm < 4; fm++)
                    av[fm] = Af[ck * 512 + (ks * 8 + wm * 4 + fm) * 32 + lane];
#pragma unroll
                for (int fn = 0; fn < 8; fn++) {
                    uint2 bv = Bf[ck * 1024 + (ks * 16 + wn * 8 + fn) * 32 + lane];
#pragma unroll
                    for (int fm = 0; fm < 4; fm++)
                        mma16(acc[fm][fn], (const uint32_t*)&av[fm], (const uint32_t*)&bv);
                }
            }
        }
        if (c8 == 7) {
#pragma unroll
            for (int fm = 0; fm < 4; fm++)
#pragma unroll
            for (int cp = 0; cp < 2; cp++) {
                const int rl = wm * 64 + fm * 16 + cp * 8 + (lane >> 2);
                const int m = m0 + rl;
                const float2 S1c  = conjf(g_S1y[m]);
                const float2 S64c = conjf(g_S64y[m]);
                const float2 EYp  = g_S128y[m];
                const int a2 = ((nt & 1) << 1) | wn;
                float2 S2c = cmulf(S1c, S1c);
                float2 pb = cmulf(cmulf(EYp, cpow4(S64c, a2)), cpow4(S2c, lane & 3));
                float2 S8c = cmulf(S2c, S2c); S8c = cmulf(S8c, S8c);
                float tx = 0.f, ty = 0.f;
#pragma unroll
                for (int fn = 0; fn < 8; fn++) {
                    float v0 = acc[fm][fn][cp * 2 + 0];
                    float v1 = acc[fm][fn][cp * 2 + 1];
                    float2 p1 = cmulf(pb, S1c);
                    if (nt < 2) { tx += v0 * pb.x + v1 * p1.x;  ty += v0 * pb.y + v1 * p1.y; }
                    else        { tx -= v0 * pb.y + v1 * p1.y;  ty += v0 * pb.x + v1 * p1.x; }
                    pb = cmulf(pb, S8c);
                }
                tx += __shfl_xor_sync(0xffffffffu, tx, 1);
                ty += __shfl_xor_sync(0xffffffffu, ty, 1);
                tx += __shfl_xor_sync(0xffffffffu, tx, 2);
                ty += __shfl_xor_sync(0xffffffffu, ty, 2);
                if ((lane & 3) == 0) {
                    t_acc[wn * 128 + rl].x += tx;
                    t_acc[wn * 128 + rl].y += ty;
                }
            }
#pragma unroll
            for (int i = 0; i < 4; i++)
#pragma unroll
                for (int j = 0; j < 8; j++)
#pragma unroll
                    for (int q = 0; q < 4; q++) acc[i][j][q] = 0.f;
        }
        asm volatile("cp.async.wait_group 0;");
        __syncthreads();
    }

    {
        const int m = m0 + tid;
        float2 t = make_float2(t_acc[tid].x + t_acc[128 + tid].x,
                               t_acc[tid].y + t_acc[128 + tid].y);
        const float lam = 1.0f / (1.0f + expf(-lamp[0]));
        const float kx = kxs[m], ky = kys[m];
        const float dcf = sqrtf(kx * kx + ky * ky);
        const int sp = m / 640, sam = m - sp * 640;
        const float2 y = yrad[sam * 288 + sp];
        const float w = lam * dcf * ORTHO;
        float2 kdc = make_float2(fmaf(w, t.x, (1.f - lam) * y.x),
                                 fmaf(w, t.y, (1.f - lam) * y.y));
        g_E0[m] = cmulf(kdc, conjf(g_S128y[m]));
    }
}

// ---------------------------------------------------------------------------
// Adjoint GEMM, ±k paired: K = 2 per rep; 40 stages of 32 reps (64 K).
// A rep-tiles cp.async; B combines G(m) and conj-partner G(m') per rep.
// ---------------------------------------------------------------------------
__global__ __launch_bounds__(128)
void adj_gemm()
{
    extern __shared__ __half sh[];
    __half* As = sh;            // 2 x 8192
    __half* Bs = sh + 16384;    // 2 x 8192

    const int tid = threadIdx.x, lane = tid & 31, wid = tid >> 5;
    const int wm = wid >> 1, wn = wid & 1;
    const int split = blockIdx.x, ut = blockIdx.y, nt = blockIdx.z;
    const int gm = tid >> 3, sub = tid & 7;
    const bool isRe = (nt < 2);
    const int yb = nt & 1;
    const int bks = gm >> 3, bklane = gm & 3, bkh8 = (gm >> 2) & 1;

    float acc[4][8][4];
#pragma unroll
    for (int i = 0; i < 4; i++)
#pragma unroll
        for (int j = 0; j < 8; j++)
#pragma unroll
            for (int q = 0; q < 4; q++) acc[i][j][q] = 0.f;

#define ADJ_FETCH(st_) do {                                                         \
    if ((st_) < ADJ_ST3) {                                                          \
        int b_ = (st_) & 1;                                                         \
        const __half* sA = g_AA + (((size_t)(split * (2*ADJ_ST3) + 2*(st_)) * 2) + ut) * 4096; \
        uint32_t dA = su32(As + b_ * 8192);                                         \
        for (int i_ = 0; i_ < 4; i_++) {                                            \
            cp16(dA + (i_ * 128 + tid) * 16, sA + (i_ * 128 + tid) * 8);            \
            cp16(dA + 8192 + (i_ * 128 + tid) * 16, sA + 8192 + (i_ * 128 + tid) * 8); \
        }                                                                           \
    }                                                                               \
    asm volatile("cp.async.commit_group;");                                         \
} while (0)

    float2 tE[2], tE2[2], tPy[2], tS8[2];
#define ADJ_TAB(st_) do {                                                   \
    _Pragma("unroll")                                                       \
    for (int c_ = 0; c_ < 2; c_++) {                                        \
        int rm_ = (split * (2*ADJ_ST3) + 2*(st_) + c_) * 16 + gm;           \
        int sp_ = rm_ / 320;                                                \
        int r_  = rm_ - sp_ * 320;                                          \
        int m_  = rm_ + sp_ * 320;                                          \
        tE[c_]  = g_E0[m_];                                                 \
        tE2[c_] = (r_ == 0) ? make_float2(0.f, 0.f)                         \
                            : g_E0[sp_ * 640 + 640 - r_];                   \
        tPy[c_] = g_PYB[(size_t)m_ * 16 + yb * 8 + sub];                    \
        tS8[c_] = g_S8y[m_];                                                \
    }                                                                       \
} while (0)

// per rep: c = G_m(v) chain, d = G_m'(v) = conj-phase chain.
// re-cols: B[2p]=c.x+d.x, B[2p+1]=d.y-c.y ; im-cols: B[2p]=c.y+d.y, B[2p+1]=c.x-d.x
#define ADJ_GENB(st_) do {                                                  \
    __half2* Bp = (__half2*)(Bs + ((st_) & 1) * 8192);                      \
    _Pragma("unroll")                                                       \
    for (int c_ = 0; c_ < 2; c_++) {                                        \
        float2 s16  = cmulf(tS8[c_], tS8[c_]);                              \
        float2 s16c = conjf(s16);                                           \
        float2 c0 = cmulf(tE[c_], tPy[c_]);                                 \
        float2 c1 = cmulf(c0, tS8[c_]);                                     \
        float2 d0 = cmulf(tE2[c_], conjf(tPy[c_]));                         \
        float2 d1 = cmulf(d0, conjf(tS8[c_]));                              \
        _Pragma("unroll")                                                   \
        for (int q2 = 0; q2 < 8; q2++) {                                    \
            int i0 = c_ * 2048 + ((bks * 16 + 2 * q2) * 32 + sub * 4 + bklane) * 2 + bkh8; \
            int i1 = i0 + 64;                                               \
            if (isRe) {                                                     \
                Bp[i0] = __halves2half2(__float2half_rn(c0.x + d0.x),       \
                                        __float2half_rn(d0.y - c0.y));      \
                Bp[i1] = __halves2half2(__float2half_rn(c1.x + d1.x),       \
                                        __float2half_rn(d1.y - c1.y));      \
            } else {                                                        \
                Bp[i0] = __halves2half2(__float2half_rn(c0.y + d0.y),       \
                                        __float2half_rn(c0.x - d0.x));      \
                Bp[i1] = __halves2half2(__float2half_rn(c1.y + d1.y),       \
                                        __float2half_rn(c1.x - d1.x));      \
            }                                                               \
            c0 = cmulf(c0, s16);  c1 = cmulf(c1, s16);                      \
            d0 = cmulf(d0, s16c); d1 = cmulf(d1, s16c);                     \
        }                                                                   \
    }                                                                       \
} while (0)

    ADJ_FETCH(0);
    ADJ_TAB(0); ADJ_GENB(0);
    ADJ_TAB(1);
    asm volatile("cp.async.wait_group 0;");
    __syncthreads();

    for (int st = 0; st < ADJ_ST3; st++) {
        ADJ_FETCH(st + 1);
        if (st + 1 < ADJ_ST3) ADJ_GENB(st + 1);
        if (st + 2 < ADJ_ST3) ADJ_TAB(st + 2);
        {
            const uint4* Af = (const uint4*)(As + (st & 1) * 8192);
            const uint2* Bf = (const uint2*)(Bs + (st & 1) * 8192);
#pragma unroll
            for (int ck = 0; ck < 2; ck++) {
#pragma unroll
                for (int ks = 0; ks < 2; ks++) {
                    uint4 av[4];
#pragma unroll
                    for (int fm = 0; fm < 4; fm++)
                        av[fm] = Af[ck * 512 + (ks * 8 + wm * 4 + fm) * 32 + lane];
#pragma unroll
                    for (int fn = 0; fn < 8; fn++) {
                        uint2 bv = Bf[ck * 1024 + (ks * 16 + wn * 8 + fn) * 32 + lane];
#pragma unroll
                        for (int fm = 0; fm < 4; fm++)
                            mma16(acc[fm][fn], (const uint32_t*)&av[fm], (const uint32_t*)&bv);
                    }
                }
            }
        }
        asm volatile("cp.async.wait_group 0;");
        __syncthreads();
    }

    float* outp = g_P + (size_t)((ut * 4 + nt) * NSPLIT + split) * 16384;
#pragma unroll
    for (int fm = 0; fm < 4; fm++)
#pragma unroll
    for (int cp = 0; cp < 2; cp++) {
        const int u = wm * 64 + fm * 16 + cp * 8 + (lane >> 2);
#pragma unroll
        for (int fn = 0; fn < 8; fn++) {
            const int n = wn * 64 + fn * 8 + 2 * (lane & 3);
            *(float2*)&outp[u * 128 + n] =
                make_float2(acc[fm][fn][cp * 2], acc[fm][fn][cp * 2 + 1]);
        }
    }
}

// ---------------------------------------------------------------------------
__global__ __launch_bounds__(256) void reduce_k(float* __restrict__ out)
{
    const int idx = blockIdx.x * 256 + threadIdx.x;
    const int ug = idx >> 9, ng = idx & 511;
    const int ut = ug >> 7, ul = ug & 127, nt = ng >> 7, nl = ng & 127;
    const float* p = g_P + (size_t)((ut * 4 + nt) * NSPLIT) * 16384 + ul * 128 + nl;
    float s = 0.f;
#pragma unroll 8
    for (int sp = 0; sp < NSPLIT; sp++) s += p[(size_t)sp * 16384];
    const int v = ng & 255, c = ng >> 8;
    const float2 corr = g_corr[0];
    s += (c == 0) ? corr.x : corr.y;
    out[(ug * 256 + v) * 2 + c] = s * ORTHO;
}

// ---------------------------------------------------------------------------
extern "C" void kernel_launch(void* const* d_in, const int* in_sizes, int n_in,
                              void* d_out, int out_size)
{
    const float2* img  = (const float2*)d_in[0];
    const float2* yrad = (const float2*)d_in[1];
    const float*  lamp = (const float*)d_in[2];
    const float*  ktr  = (const float*)d_in[3];
    const float*  kxs  = ktr;
    const float*  kys  = ktr + MTOT;
    float* out = (float*)d_out;

    const int FWD_SMEM = 32768 * 2 + 256 * 8;   // 67584 B
    const int ADJ_SMEM = 32768 * 2;             // 65536 B
    cudaFuncSetAttribute(fwd_gemm, cudaFuncAttributeMaxDynamicSharedMemorySize, FWD_SMEM);
    cudaFuncSetAttribute(adj_gemm, cudaFuncAttributeMaxDynamicSharedMemorySize, ADJ_SMEM);

    prep_tab<<<MTOT/256, 256>>>(kxs, kys);
    prep_bf<<<1024, 256>>>(img);
    prep_fa<<<dim3(NMT, 16), 128>>>();
    prep_aa<<<dim3(NKSTA, 2), 128>>>();
    fwd_gemm<<<NMT, 128, FWD_SMEM>>>(yrad, lamp, kxs, kys);
    corr_k<<<1, 512>>>();
    adj_gemm<<<dim3(NSPLIT, 2, 4), 128, ADJ_SMEM>>>();
    reduce_k<<<512, 256>>>(out);
}